// round 1
// baseline (speedup 1.0000x reference)
#include <cuda_runtime.h>
#include <math_constants.h>

#define BB 4
#define TT 2048
#define CC 1024
#define HH 64

// Scratch for projected Q, K, V (2 MB each)
__device__ float g_Q[BB*TT*HH];
__device__ float g_K[BB*TT*HH];
__device__ float g_V[BB*TT*HH];

// ---------------------------------------------------------------------------
// Projection GEMM: O[8192,64] = X[8192,1024] @ W[1024,64], z selects q/k/v.
// 64x64 output tile per block, 256 threads, 4x4 microtile per thread.
// ---------------------------------------------------------------------------
__global__ __launch_bounds__(256) void proj_kernel(
    const float* __restrict__ q, const float* __restrict__ k, const float* __restrict__ v,
    const float* __restrict__ Wq, const float* __restrict__ Wk, const float* __restrict__ Wv)
{
    int z = blockIdx.y;
    const float* X = (z == 0) ? q : (z == 1) ? k : v;
    const float* W = (z == 0) ? Wq : (z == 1) ? Wk : Wv;
    float* O = (z == 0) ? g_Q : (z == 1) ? g_K : g_V;

    int row0 = blockIdx.x * 64;

    __shared__ float sX[64][68];
    __shared__ float sW[64][68];

    int t = threadIdx.x;
    int r = t >> 4;      // 0..15 -> rows {r, r+16, r+32, r+48}
    int c = t & 15;      // 0..15 -> cols {c, c+16, c+32, c+48}

    float acc[4][4];
#pragma unroll
    for (int m = 0; m < 4; m++)
#pragma unroll
        for (int n = 0; n < 4; n++) acc[m][n] = 0.f;

    for (int k0 = 0; k0 < CC; k0 += 64) {
#pragma unroll
        for (int i = 0; i < 4; i++) {
            int idx = t + i * 256;          // 1024 float4 per tile
            int rr = idx >> 4, cc = idx & 15;
            *(float4*)&sX[rr][cc * 4] =
                *(const float4*)&X[(size_t)(row0 + rr) * CC + k0 + cc * 4];
            *(float4*)&sW[rr][cc * 4] =
                *(const float4*)&W[(size_t)(k0 + rr) * HH + cc * 4];
        }
        __syncthreads();

#pragma unroll
        for (int kk = 0; kk < 64; kk += 4) {
            float4 xv[4];
#pragma unroll
            for (int m = 0; m < 4; m++) xv[m] = *(float4*)&sX[r + 16 * m][kk];
#pragma unroll
            for (int d = 0; d < 4; d++) {
                float w0 = sW[kk + d][c];
                float w1 = sW[kk + d][c + 16];
                float w2 = sW[kk + d][c + 32];
                float w3 = sW[kk + d][c + 48];
#pragma unroll
                for (int m = 0; m < 4; m++) {
                    float x = ((const float*)&xv[m])[d];
                    acc[m][0] += x * w0;
                    acc[m][1] += x * w1;
                    acc[m][2] += x * w2;
                    acc[m][3] += x * w3;
                }
            }
        }
        __syncthreads();
    }

#pragma unroll
    for (int m = 0; m < 4; m++)
#pragma unroll
        for (int n = 0; n < 4; n++)
            O[(size_t)(row0 + r + 16 * m) * HH + c + 16 * n] = acc[m][n];
}

// ---------------------------------------------------------------------------
// Flash attention with masked_fill(1e-9) semantics.
// Block: 32 query rows, 256 threads. Each thread owns rows {r, r+16},
// score/output columns {c, c+16, c+32, c+48}. Only kept KV tiles are
// processed; the fully-masked suffix is folded in via a V suffix-sum.
// ---------------------------------------------------------------------------
__global__ __launch_bounds__(256) void attn_kernel(const int* __restrict__ pad,
                                                   float* __restrict__ out)
{
    int bid = blockIdx.x;
    int b  = bid & 3;
    int qt = 63 - (bid >> 2);     // longest blocks launch first
    int qi0 = qt * 32;

    const float* Q = g_Q + (size_t)b * TT * HH;
    const float* K = g_K + (size_t)b * TT * HH;
    const float* V = g_V + (size_t)b * TT * HH;

    __shared__ float sQ[32][68];
    __shared__ float sK[64][68];
    __shared__ float sV[64][65];
    __shared__ float sVp[4][64];

    int t = threadIdx.x;
    int r = t >> 4;   // 0..15
    int c = t & 15;   // 0..15

    // Load Q tile (32 x 64)
#pragma unroll
    for (int i = 0; i < 2; i++) {
        int idx = t + i * 256;
        int rr = idx >> 4, cc = idx & 15;
        *(float4*)&sQ[rr][cc * 4] =
            *(const float4*)&Q[(size_t)(qi0 + rr) * HH + cc * 4];
    }
    bool padr[2];
    padr[0] = (pad[b * TT + qi0 + r] == 1);
    padr[1] = (pad[b * TT + qi0 + r + 16] == 1);
    __syncthreads();

    const float scale = 0.125f;                 // 64^-0.5
    const float CMv   = 1e-9f * 0.125f;         // masked logit after scaling

    float m_i[2] = {-CUDART_INF_F, -CUDART_INF_F};
    float l_i[2] = {0.f, 0.f};
    float Oa[2][4];
#pragma unroll
    for (int m = 0; m < 2; m++)
#pragma unroll
        for (int n = 0; n < 4; n++) Oa[m][n] = 0.f;

    // KV tiles that contain at least one kept element
    int kt_end = (qi0 + 32) / 64 + 1;
    if (kt_end > 32) kt_end = 32;

    for (int kt = 0; kt < kt_end; kt++) {
        int kj0 = kt * 64;
        // Load K (float4, stride 68) and V (scalar stores, stride 65)
#pragma unroll
        for (int i = 0; i < 4; i++) {
            int idx = t + i * 256;
            int rr = idx >> 4, cc = idx & 15;
            *(float4*)&sK[rr][cc * 4] =
                *(const float4*)&K[(size_t)(kj0 + rr) * HH + cc * 4];
            float4 vv = *(const float4*)&V[(size_t)(kj0 + rr) * HH + cc * 4];
            sV[rr][cc * 4 + 0] = vv.x;
            sV[rr][cc * 4 + 1] = vv.y;
            sV[rr][cc * 4 + 2] = vv.z;
            sV[rr][cc * 4 + 3] = vv.w;
        }
        __syncthreads();

        // S = Q K^T (2x4 microtile)
        float s[2][4];
#pragma unroll
        for (int m = 0; m < 2; m++)
#pragma unroll
            for (int n = 0; n < 4; n++) s[m][n] = 0.f;

#pragma unroll
        for (int kk = 0; kk < 64; kk += 4) {
            float4 q0 = *(float4*)&sQ[r][kk];
            float4 q1 = *(float4*)&sQ[r + 16][kk];
            float4 kv[4];
#pragma unroll
            for (int n = 0; n < 4; n++) kv[n] = *(float4*)&sK[c + 16 * n][kk];
#pragma unroll
            for (int n = 0; n < 4; n++) {
                s[0][n] += q0.x * kv[n].x + q0.y * kv[n].y + q0.z * kv[n].z + q0.w * kv[n].w;
                s[1][n] += q1.x * kv[n].x + q1.y * kv[n].y + q1.z * kv[n].z + q1.w * kv[n].w;
            }
        }

        // Mask + scale, row max
        float tmax[2] = {-CUDART_INF_F, -CUDART_INF_F};
#pragma unroll
        for (int m = 0; m < 2; m++) {
            int row = qi0 + r + 16 * m;
#pragma unroll
            for (int n = 0; n < 4; n++) {
                int col = kj0 + c + 16 * n;
                bool keep = (col <= row + 1) && !padr[m];
                s[m][n] = keep ? s[m][n] * scale : CMv;
                tmax[m] = fmaxf(tmax[m], s[m][n]);
            }
        }
#pragma unroll
        for (int o = 1; o < 16; o <<= 1) {
            tmax[0] = fmaxf(tmax[0], __shfl_xor_sync(0xffffffffu, tmax[0], o, 16));
            tmax[1] = fmaxf(tmax[1], __shfl_xor_sync(0xffffffffu, tmax[1], o, 16));
        }

        float fac[2], tsum[2] = {0.f, 0.f};
#pragma unroll
        for (int m = 0; m < 2; m++) {
            float mnew = fmaxf(m_i[m], tmax[m]);
            fac[m] = __expf(m_i[m] - mnew);
            m_i[m] = mnew;
        }
#pragma unroll
        for (int m = 0; m < 2; m++)
#pragma unroll
            for (int n = 0; n < 4; n++) {
                s[m][n] = __expf(s[m][n] - m_i[m]);
                tsum[m] += s[m][n];
            }
#pragma unroll
        for (int o = 1; o < 16; o <<= 1) {
            tsum[0] += __shfl_xor_sync(0xffffffffu, tsum[0], o, 16);
            tsum[1] += __shfl_xor_sync(0xffffffffu, tsum[1], o, 16);
        }
#pragma unroll
        for (int m = 0; m < 2; m++) {
            l_i[m] = l_i[m] * fac[m] + tsum[m];
#pragma unroll
            for (int n = 0; n < 4; n++) Oa[m][n] *= fac[m];
        }

        // O += P @ V  (P distributed across the 16-lane row group via shfl)
#pragma unroll
        for (int col = 0; col < 64; col++) {
            int n = col >> 4, sl = col & 15;
            float p0 = __shfl_sync(0xffffffffu, s[0][n], sl, 16);
            float p1 = __shfl_sync(0xffffffffu, s[1][n], sl, 16);
            float v0 = sV[col][c];
            float v1 = sV[col][c + 16];
            float v2 = sV[col][c + 32];
            float v3 = sV[col][c + 48];
            Oa[0][0] += p0 * v0; Oa[0][1] += p0 * v1; Oa[0][2] += p0 * v2; Oa[0][3] += p0 * v3;
            Oa[1][0] += p1 * v0; Oa[1][1] += p1 * v1; Oa[1][2] += p1 * v2; Oa[1][3] += p1 * v3;
        }
        __syncthreads();
    }

    // Fully-masked suffix: every col in [mask_start, T) has logit CMv for all
    // rows in this tile -> closed-form softmax update with a V column sum.
    int mask_start = kt_end * 64;
    if (mask_start < TT) {
        int h = t & 63, g = t >> 6;
        float a = 0.f;
        for (int j = mask_start + g; j < TT; j += 4)
            a += V[(size_t)j * HH + h];
        sVp[g][h] = a;
        __syncthreads();

        float n_mask = (float)(TT - mask_start);
#pragma unroll
        for (int m = 0; m < 2; m++) {
            float mnew = fmaxf(m_i[m], CMv);
            float f = __expf(m_i[m] - mnew);
            float w = __expf(CMv - mnew);
            l_i[m] = l_i[m] * f + n_mask * w;
#pragma unroll
            for (int n = 0; n < 4; n++) {
                int col = c + 16 * n;
                float vs = sVp[0][col] + sVp[1][col] + sVp[2][col] + sVp[3][col];
                Oa[m][n] = Oa[m][n] * f + w * vs;
            }
            m_i[m] = mnew;
        }
    }

    // Epilogue
#pragma unroll
    for (int m = 0; m < 2; m++) {
        float inv = 1.f / l_i[m];
        int row = qi0 + r + 16 * m;
#pragma unroll
        for (int n = 0; n < 4; n++)
            out[(size_t)(b * TT + row) * HH + c + 16 * n] = Oa[m][n] * inv;
    }
}

extern "C" void kernel_launch(void* const* d_in, const int* in_sizes, int n_in,
                              void* d_out, int out_size)
{
    const float* q  = (const float*)d_in[0];
    const float* k  = (const float*)d_in[1];
    const float* v  = (const float*)d_in[2];
    const float* Wq = (const float*)d_in[3];
    const float* Wk = (const float*)d_in[4];
    const float* Wv = (const float*)d_in[5];
    const int* pad  = (const int*)d_in[6];
    float* out = (float*)d_out;

    dim3 pg(128, 3);
    proj_kernel<<<pg, 256>>>(q, k, v, Wq, Wk, Wv);
    attn_kernel<<<BB * 64, 256>>>(pad, out);
}

// round 2
// speedup vs baseline: 1.0349x; 1.0349x over previous
#include <cuda_runtime.h>
#include <math_constants.h>

#define BB 4
#define TT 2048
#define CC 1024
#define HH 64

// Scratch for projected Q, K, V (2 MB each)
__device__ float g_Q[BB*TT*HH];
__device__ float g_K[BB*TT*HH];
__device__ float g_V[BB*TT*HH];

// ---------------------------------------------------------------------------
// Projection GEMM: O[8192,64] = X[8192,1024] @ W[1024,64], z selects q/k/v.
// 64x64 output tile per block, 256 threads, 4x4 microtile per thread.
// ---------------------------------------------------------------------------
__global__ __launch_bounds__(256) void proj_kernel(
    const float* __restrict__ q, const float* __restrict__ k, const float* __restrict__ v,
    const float* __restrict__ Wq, const float* __restrict__ Wk, const float* __restrict__ Wv)
{
    int z = blockIdx.y;
    const float* X = (z == 0) ? q : (z == 1) ? k : v;
    const float* W = (z == 0) ? Wq : (z == 1) ? Wk : Wv;
    float* O = (z == 0) ? g_Q : (z == 1) ? g_K : g_V;

    int row0 = blockIdx.x * 64;

    __shared__ float sX[64][68];
    __shared__ float sW[64][68];

    int t = threadIdx.x;
    int r = t >> 4;      // 0..15 -> rows {r, r+16, r+32, r+48}
    int c = t & 15;      // 0..15 -> cols {c, c+16, c+32, c+48}

    float acc[4][4];
#pragma unroll
    for (int m = 0; m < 4; m++)
#pragma unroll
        for (int n = 0; n < 4; n++) acc[m][n] = 0.f;

    for (int k0 = 0; k0 < CC; k0 += 64) {
#pragma unroll
        for (int i = 0; i < 4; i++) {
            int idx = t + i * 256;          // 1024 float4 per tile
            int rr = idx >> 4, cc = idx & 15;
            *(float4*)&sX[rr][cc * 4] =
                *(const float4*)&X[(size_t)(row0 + rr) * CC + k0 + cc * 4];
            *(float4*)&sW[rr][cc * 4] =
                *(const float4*)&W[(size_t)(k0 + rr) * HH + cc * 4];
        }
        __syncthreads();

#pragma unroll
        for (int kk = 0; kk < 64; kk += 4) {
            float4 xv[4];
#pragma unroll
            for (int m = 0; m < 4; m++) xv[m] = *(float4*)&sX[r + 16 * m][kk];
#pragma unroll
            for (int d = 0; d < 4; d++) {
                float w0 = sW[kk + d][c];
                float w1 = sW[kk + d][c + 16];
                float w2 = sW[kk + d][c + 32];
                float w3 = sW[kk + d][c + 48];
#pragma unroll
                for (int m = 0; m < 4; m++) {
                    float x = ((const float*)&xv[m])[d];
                    acc[m][0] += x * w0;
                    acc[m][1] += x * w1;
                    acc[m][2] += x * w2;
                    acc[m][3] += x * w3;
                }
            }
        }
        __syncthreads();
    }

#pragma unroll
    for (int m = 0; m < 4; m++)
#pragma unroll
        for (int n = 0; n < 4; n++)
            O[(size_t)(row0 + r + 16 * m) * HH + c + 16 * n] = acc[m][n];
}

// ---------------------------------------------------------------------------
// Flash attention with masked_fill(1e-9) semantics.
// Block: 32 query rows, 256 threads. Each thread owns rows {r, r+16},
// score/output columns {c, c+16, c+32, c+48}. Only kept KV tiles are
// processed; the fully-masked suffix is folded in via a V suffix-sum.
// ---------------------------------------------------------------------------
__global__ __launch_bounds__(256) void attn_kernel(const int* __restrict__ pad,
                                                   float* __restrict__ out)
{
    int bid = blockIdx.x;
    int b  = bid & 3;
    int qt = 63 - (bid >> 2);     // longest blocks launch first
    int qi0 = qt * 32;

    const float* Q = g_Q + (size_t)b * TT * HH;
    const float* K = g_K + (size_t)b * TT * HH;
    const float* V = g_V + (size_t)b * TT * HH;

    __shared__ float sQ[32][68];
    __shared__ float sK[64][68];
    __shared__ float sV[64][65];
    __shared__ float sVp[4][64];

    int t = threadIdx.x;
    int r = t >> 4;   // 0..15
    int c = t & 15;   // 0..15

    // Load Q tile (32 x 64)
#pragma unroll
    for (int i = 0; i < 2; i++) {
        int idx = t + i * 256;
        int rr = idx >> 4, cc = idx & 15;
        *(float4*)&sQ[rr][cc * 4] =
            *(const float4*)&Q[(size_t)(qi0 + rr) * HH + cc * 4];
    }
    bool padr[2];
    padr[0] = (pad[b * TT + qi0 + r] == 1);
    padr[1] = (pad[b * TT + qi0 + r + 16] == 1);
    __syncthreads();

    const float scale = 0.125f;                 // 64^-0.5
    const float CMv   = 1e-9f * 0.125f;         // masked logit after scaling

    float m_i[2] = {-CUDART_INF_F, -CUDART_INF_F};
    float l_i[2] = {0.f, 0.f};
    float Oa[2][4];
#pragma unroll
    for (int m = 0; m < 2; m++)
#pragma unroll
        for (int n = 0; n < 4; n++) Oa[m][n] = 0.f;

    // KV tiles that contain at least one kept element
    int kt_end = (qi0 + 32) / 64 + 1;
    if (kt_end > 32) kt_end = 32;

    for (int kt = 0; kt < kt_end; kt++) {
        int kj0 = kt * 64;
        // Load K (float4, stride 68) and V (scalar stores, stride 65)
#pragma unroll
        for (int i = 0; i < 4; i++) {
            int idx = t + i * 256;
            int rr = idx >> 4, cc = idx & 15;
            *(float4*)&sK[rr][cc * 4] =
                *(const float4*)&K[(size_t)(kj0 + rr) * HH + cc * 4];
            float4 vv = *(const float4*)&V[(size_t)(kj0 + rr) * HH + cc * 4];
            sV[rr][cc * 4 + 0] = vv.x;
            sV[rr][cc * 4 + 1] = vv.y;
            sV[rr][cc * 4 + 2] = vv.z;
            sV[rr][cc * 4 + 3] = vv.w;
        }
        __syncthreads();

        // S = Q K^T (2x4 microtile)
        float s[2][4];
#pragma unroll
        for (int m = 0; m < 2; m++)
#pragma unroll
            for (int n = 0; n < 4; n++) s[m][n] = 0.f;

#pragma unroll
        for (int kk = 0; kk < 64; kk += 4) {
            float4 q0 = *(float4*)&sQ[r][kk];
            float4 q1 = *(float4*)&sQ[r + 16][kk];
            float4 kv[4];
#pragma unroll
            for (int n = 0; n < 4; n++) kv[n] = *(float4*)&sK[c + 16 * n][kk];
#pragma unroll
            for (int n = 0; n < 4; n++) {
                s[0][n] += q0.x * kv[n].x + q0.y * kv[n].y + q0.z * kv[n].z + q0.w * kv[n].w;
                s[1][n] += q1.x * kv[n].x + q1.y * kv[n].y + q1.z * kv[n].z + q1.w * kv[n].w;
            }
        }

        // Mask + scale, row max
        float tmax[2] = {-CUDART_INF_F, -CUDART_INF_F};
#pragma unroll
        for (int m = 0; m < 2; m++) {
            int row = qi0 + r + 16 * m;
#pragma unroll
            for (int n = 0; n < 4; n++) {
                int col = kj0 + c + 16 * n;
                bool keep = (col <= row + 1) && !padr[m];
                s[m][n] = keep ? s[m][n] * scale : CMv;
                tmax[m] = fmaxf(tmax[m], s[m][n]);
            }
        }
#pragma unroll
        for (int o = 1; o < 16; o <<= 1) {
            tmax[0] = fmaxf(tmax[0], __shfl_xor_sync(0xffffffffu, tmax[0], o, 16));
            tmax[1] = fmaxf(tmax[1], __shfl_xor_sync(0xffffffffu, tmax[1], o, 16));
        }

        float fac[2], tsum[2] = {0.f, 0.f};
#pragma unroll
        for (int m = 0; m < 2; m++) {
            float mnew = fmaxf(m_i[m], tmax[m]);
            fac[m] = __expf(m_i[m] - mnew);
            m_i[m] = mnew;
        }
#pragma unroll
        for (int m = 0; m < 2; m++)
#pragma unroll
            for (int n = 0; n < 4; n++) {
                s[m][n] = __expf(s[m][n] - m_i[m]);
                tsum[m] += s[m][n];
            }
#pragma unroll
        for (int o = 1; o < 16; o <<= 1) {
            tsum[0] += __shfl_xor_sync(0xffffffffu, tsum[0], o, 16);
            tsum[1] += __shfl_xor_sync(0xffffffffu, tsum[1], o, 16);
        }
#pragma unroll
        for (int m = 0; m < 2; m++) {
            l_i[m] = l_i[m] * fac[m] + tsum[m];
#pragma unroll
            for (int n = 0; n < 4; n++) Oa[m][n] *= fac[m];
        }

        // O += P @ V  (P distributed across the 16-lane row group via shfl)
#pragma unroll
        for (int col = 0; col < 64; col++) {
            int n = col >> 4, sl = col & 15;
            float p0 = __shfl_sync(0xffffffffu, s[0][n], sl, 16);
            float p1 = __shfl_sync(0xffffffffu, s[1][n], sl, 16);
            float v0 = sV[col][c];
            float v1 = sV[col][c + 16];
            float v2 = sV[col][c + 32];
            float v3 = sV[col][c + 48];
            Oa[0][0] += p0 * v0; Oa[0][1] += p0 * v1; Oa[0][2] += p0 * v2; Oa[0][3] += p0 * v3;
            Oa[1][0] += p1 * v0; Oa[1][1] += p1 * v1; Oa[1][2] += p1 * v2; Oa[1][3] += p1 * v3;
        }
        __syncthreads();
    }

    // Fully-masked suffix: every col in [mask_start, T) has logit CMv for all
    // rows in this tile -> closed-form softmax update with a V column sum.
    int mask_start = kt_end * 64;
    if (mask_start < TT) {
        int h = t & 63, g = t >> 6;
        float a = 0.f;
        for (int j = mask_start + g; j < TT; j += 4)
            a += V[(size_t)j * HH + h];
        sVp[g][h] = a;
        __syncthreads();

        float n_mask = (float)(TT - mask_start);
#pragma unroll
        for (int m = 0; m < 2; m++) {
            float mnew = fmaxf(m_i[m], CMv);
            float f = __expf(m_i[m] - mnew);
            float w = __expf(CMv - mnew);
            l_i[m] = l_i[m] * f + n_mask * w;
#pragma unroll
            for (int n = 0; n < 4; n++) {
                int col = c + 16 * n;
                float vs = sVp[0][col] + sVp[1][col] + sVp[2][col] + sVp[3][col];
                Oa[m][n] = Oa[m][n] * f + w * vs;
            }
            m_i[m] = mnew;
        }
    }

    // Epilogue
#pragma unroll
    for (int m = 0; m < 2; m++) {
        float inv = 1.f / l_i[m];
        int row = qi0 + r + 16 * m;
#pragma unroll
        for (int n = 0; n < 4; n++)
            out[(size_t)(b * TT + row) * HH + c + 16 * n] = Oa[m][n] * inv;
    }
}

extern "C" void kernel_launch(void* const* d_in, const int* in_sizes, int n_in,
                              void* d_out, int out_size)
{
    const float* q  = (const float*)d_in[0];
    const float* k  = (const float*)d_in[1];
    const float* v  = (const float*)d_in[2];
    const float* Wq = (const float*)d_in[3];
    const float* Wk = (const float*)d_in[4];
    const float* Wv = (const float*)d_in[5];
    const int* pad  = (const int*)d_in[6];
    float* out = (float*)d_out;

    dim3 pg(128, 3);
    proj_kernel<<<pg, 256>>>(q, k, v, Wq, Wk, Wv);
    attn_kernel<<<BB * 64, 256>>>(pad, out);
}

// round 5
// speedup vs baseline: 1.2435x; 1.2017x over previous
#include <cuda_runtime.h>
#include <cstdint>

#define BB 4
#define TT 2048
#define CC 1024
#define HH 64
#define AST 68   // attn smem row stride (floats)

__device__ float g_Q[BB*TT*HH];
__device__ float g_K[BB*TT*HH];
__device__ float g_V[BB*TT*HH];
__device__ float g_Wt[3][HH*CC];
__device__ float g_Vtile[BB][32][HH];
__device__ float g_Vpre[BB][33][HH];
__device__ float g_accO[4][BB*TT*HH];
__device__ float g_accL[4][BB*TT];

// ---------------- W transpose: g_Wt[z][n*CC + k] = W_z[k*HH + n] ----------------
__global__ void wt_kernel(const float* __restrict__ Wq, const float* __restrict__ Wk,
                          const float* __restrict__ Wv)
{
    int z = blockIdx.x;
    const float* W = (z == 0) ? Wq : (z == 1) ? Wk : Wv;
    float* Wt = g_Wt[z];
    int k0 = blockIdx.y * 256;
    for (int i = threadIdx.x; i < 256 * 16; i += 256) {
        int k = k0 + (i >> 4), n4 = (i & 15) << 2;
        float4 w = *(const float4*)&W[(size_t)k * HH + n4];
        Wt[(size_t)(n4 + 0) * CC + k] = w.x;
        Wt[(size_t)(n4 + 1) * CC + k] = w.y;
        Wt[(size_t)(n4 + 2) * CC + k] = w.z;
        Wt[(size_t)(n4 + 3) * CC + k] = w.w;
    }
}

// ---------------- Projection GEMM (SIMT fp32, both operands K-major) ----------------
__global__ __launch_bounds__(256) void proj_kernel(
    const float* __restrict__ q, const float* __restrict__ k, const float* __restrict__ v)
{
    int z = blockIdx.y;
    const float* X = (z == 0) ? q : (z == 1) ? k : v;
    float* O = (z == 0) ? g_Q : (z == 1) ? g_K : g_V;
    const float* Wt = g_Wt[z];
    int row0 = blockIdx.x * 64;

    __shared__ float sX[64][AST];
    __shared__ float sW[64][AST];

    int t = threadIdx.x;
    int r = t >> 4, c = t & 15;

    float acc[4][4];
#pragma unroll
    for (int m = 0; m < 4; m++)
#pragma unroll
        for (int n = 0; n < 4; n++) acc[m][n] = 0.f;

    for (int k0 = 0; k0 < CC; k0 += 64) {
#pragma unroll
        for (int i = 0; i < 4; i++) {
            int idx = t + i * 256;
            int rr = idx >> 4, cc = (idx & 15) << 2;
            *(float4*)&sX[rr][cc] = *(const float4*)&X[(size_t)(row0 + rr) * CC + k0 + cc];
            *(float4*)&sW[rr][cc] = *(const float4*)&Wt[(size_t)rr * CC + k0 + cc];
        }
        __syncthreads();

#pragma unroll
        for (int kk = 0; kk < 64; kk += 4) {
            float4 xv[4], wv[4];
#pragma unroll
            for (int m = 0; m < 4; m++) xv[m] = *(float4*)&sX[r + 16 * m][kk];
#pragma unroll
            for (int n = 0; n < 4; n++) wv[n] = *(float4*)&sW[c + 16 * n][kk];
#pragma unroll
            for (int m = 0; m < 4; m++)
#pragma unroll
                for (int n = 0; n < 4; n++)
                    acc[m][n] += xv[m].x * wv[n].x + xv[m].y * wv[n].y
                               + xv[m].z * wv[n].z + xv[m].w * wv[n].w;
        }
        __syncthreads();
    }

#pragma unroll
    for (int m = 0; m < 4; m++)
#pragma unroll
        for (int n = 0; n < 4; n++)
            O[(size_t)(row0 + r + 16 * m) * HH + c + 16 * n] = acc[m][n];
}

// ---------------- V tile sums + prefix ----------------
__global__ void vtile_kernel() {
    int b = blockIdx.x, kt = blockIdx.y, h = threadIdx.x;
    const float* V = g_V + ((size_t)b * TT + kt * 64) * HH;
    float a = 0.f;
#pragma unroll 8
    for (int j = 0; j < 64; j++) a += V[j * HH + h];
    g_Vtile[b][kt][h] = a;
}
__global__ void vpre_kernel() {
    int t = threadIdx.x, b = t >> 6, h = t & 63;
    float run = 0.f;
#pragma unroll
    for (int kt = 0; kt < 32; kt++) { g_Vpre[b][kt][h] = run; run += g_Vtile[b][kt][h]; }
    g_Vpre[b][32][h] = run;
}

// ---------------- Attention: split-KV, fixed exp basis ----------------
// masked weight = expf(1.25e-10) == 1.0f exactly; kept weight = expf(s*0.125).
__global__ __launch_bounds__(256) void attn_kernel(const int* __restrict__ pad)
{
    extern __shared__ float smem[];
    float* sQ = smem;                    // 64 x AST
    float* sK = smem + 64 * AST;
    float* sV = smem + 2 * 64 * AST;
    float* sP = smem + 3 * 64 * AST;

    // unit -> (b, qt, chunk); batches interleaved, longest q-tiles first
    int u = blockIdx.x;
    int b = u & 3, w = u >> 2;
    int qt = 0, chunk = 0, rem = w;
#pragma unroll 1
    for (int q2 = 31; q2 >= 0; q2--) {
        int kte = q2 + 2; if (kte > 32) kte = 32;
        int s = (kte + 7) >> 3;
        if (rem < s) { qt = q2; chunk = rem; break; }
        rem -= s;
    }
    int kt_end = qt + 2; if (kt_end > 32) kt_end = 32;
    int kt0 = chunk * 8, kt1 = kt0 + 8; if (kt1 > kt_end) kt1 = kt_end;
    bool last = (kt1 == kt_end);
    int qi0 = qt * 64;

    const float* Q = g_Q + (size_t)b * TT * HH;
    const float* K = g_K + (size_t)b * TT * HH;
    const float* V = g_V + (size_t)b * TT * HH;

    int t = threadIdx.x;
    int r = t >> 4, c = t & 15;

#pragma unroll
    for (int i = 0; i < 4; i++) {
        int idx = i * 256 + t;
        int rr = idx >> 4, cc = (idx & 15) << 2;
        *(float4*)&sQ[rr * AST + cc] = *(const float4*)&Q[(size_t)(qi0 + rr) * HH + cc];
    }
    bool padr[4];
#pragma unroll
    for (int m = 0; m < 4; m++) padr[m] = (pad[b * TT + qi0 + r + 16 * m] == 1);

    float4 Oa[4];
    float lp[4];
#pragma unroll
    for (int m = 0; m < 4; m++) { Oa[m] = make_float4(0.f,0.f,0.f,0.f); lp[m] = 0.f; }

#pragma unroll 1
    for (int kt = kt0; kt < kt1; kt++) {
        int kj0 = kt * 64;
        __syncthreads();                           // prior PV done before overwrite
#pragma unroll
        for (int i = 0; i < 4; i++) {
            int idx = i * 256 + t;
            int rr = idx >> 4, cc = (idx & 15) << 2;
            *(float4*)&sK[rr * AST + cc] = *(const float4*)&K[(size_t)(kj0 + rr) * HH + cc];
            *(float4*)&sV[rr * AST + cc] = *(const float4*)&V[(size_t)(kj0 + rr) * HH + cc];
        }
        __syncthreads();

        float s[4][4];
#pragma unroll
        for (int m = 0; m < 4; m++)
#pragma unroll
            for (int n = 0; n < 4; n++) s[m][n] = 0.f;
#pragma unroll
        for (int kk = 0; kk < 64; kk += 4) {
            float4 qv[4], kv[4];
#pragma unroll
            for (int m = 0; m < 4; m++) qv[m] = *(float4*)&sQ[(r + 16 * m) * AST + kk];
#pragma unroll
            for (int n = 0; n < 4; n++) kv[n] = *(float4*)&sK[(c + 16 * n) * AST + kk];
#pragma unroll
            for (int m = 0; m < 4; m++)
#pragma unroll
                for (int n = 0; n < 4; n++)
                    s[m][n] += qv[m].x*kv[n].x + qv[m].y*kv[n].y
                             + qv[m].z*kv[n].z + qv[m].w*kv[n].w;
        }
#pragma unroll
        for (int m = 0; m < 4; m++) {
            int row = qi0 + r + 16 * m;
#pragma unroll
            for (int n = 0; n < 4; n++) {
                int col = kj0 + c + 16 * n;
                float wv = ((col <= row + 1) && !padr[m]) ? __expf(s[m][n] * 0.125f) : 1.0f;
                lp[m] += wv;
                sP[(r + 16 * m) * AST + c + 16 * n] = wv;
            }
        }
        __syncthreads();
        // O += P @ V   (thread owns output cols c*4..c*4+3)
#pragma unroll
        for (int kk = 0; kk < 64; kk += 4) {
            float4 pv[4], vv[4];
#pragma unroll
            for (int m = 0; m < 4; m++) pv[m] = *(float4*)&sP[(r + 16 * m) * AST + kk];
#pragma unroll
            for (int d = 0; d < 4; d++) vv[d] = *(float4*)&sV[(kk + d) * AST + (c << 2)];
#pragma unroll
            for (int m = 0; m < 4; m++) {
                Oa[m].x += pv[m].x*vv[0].x + pv[m].y*vv[1].x + pv[m].z*vv[2].x + pv[m].w*vv[3].x;
                Oa[m].y += pv[m].x*vv[0].y + pv[m].y*vv[1].y + pv[m].z*vv[2].y + pv[m].w*vv[3].y;
                Oa[m].z += pv[m].x*vv[0].z + pv[m].y*vv[1].z + pv[m].z*vv[2].z + pv[m].w*vv[3].z;
                Oa[m].w += pv[m].x*vv[0].w + pv[m].y*vv[1].w + pv[m].z*vv[2].w + pv[m].w*vv[3].w;
            }
        }
    }

    // row-sum l over the 16 col-lanes
#pragma unroll
    for (int m = 0; m < 4; m++)
#pragma unroll
        for (int o = 1; o < 16; o <<= 1)
            lp[m] += __shfl_xor_sync(0xffffffffu, lp[m], o, 16);

    // fully-masked suffix (weight exactly 1.0 each): count + V column-sums
    if (last && kt_end < 32) {
        float4 tot = *(float4*)&g_Vpre[b][32][c << 2];
        float4 pre = *(float4*)&g_Vpre[b][kt_end][c << 2];
        float4 suf = make_float4(tot.x - pre.x, tot.y - pre.y, tot.z - pre.z, tot.w - pre.w);
        float cnt = (float)(TT - kt_end * 64);
#pragma unroll
        for (int m = 0; m < 4; m++) {
            Oa[m].x += suf.x; Oa[m].y += suf.y; Oa[m].z += suf.z; Oa[m].w += suf.w;
            lp[m] += cnt;
        }
    }

#pragma unroll
    for (int m = 0; m < 4; m++) {
        size_t row = (size_t)b * TT + qi0 + r + 16 * m;
        *(float4*)&g_accO[chunk][row * HH + (c << 2)] = Oa[m];
        if (c == 0) g_accL[chunk][row] = lp[m];
    }
}

// ---------------- combine partials, divide ----------------
__global__ void final_kernel(float* __restrict__ out)
{
    int idx = blockIdx.x * 256 + threadIdx.x;     // float4 index over B*T*16
    int row = idx >> 4;
    int qt = (row & (TT - 1)) >> 6;
    int kte = qt + 2; if (kte > 32) kte = 32;
    int ns = (kte + 7) >> 3;
    float l = 0.f;
    float4 o = make_float4(0.f,0.f,0.f,0.f);
#pragma unroll 1
    for (int s = 0; s < ns; s++) {
        l += g_accL[s][row];
        float4 p = ((const float4*)g_accO[s])[idx];
        o.x += p.x; o.y += p.y; o.z += p.z; o.w += p.w;
    }
    float inv = 1.f / l;
    ((float4*)out)[idx] = make_float4(o.x*inv, o.y*inv, o.z*inv, o.w*inv);
}

extern "C" void kernel_launch(void* const* d_in, const int* in_sizes, int n_in,
                              void* d_out, int out_size)
{
    const float* q  = (const float*)d_in[0];
    const float* k  = (const float*)d_in[1];
    const float* v  = (const float*)d_in[2];
    const float* Wq = (const float*)d_in[3];
    const float* Wk = (const float*)d_in[4];
    const float* Wv = (const float*)d_in[5];
    const int* pad  = (const int*)d_in[6];
    float* out = (float*)d_out;

    const int attn_smem = 4 * 64 * AST * (int)sizeof(float);   // 69,632 B
    cudaFuncSetAttribute(attn_kernel, cudaFuncAttributeMaxDynamicSharedMemorySize, attn_smem);

    wt_kernel<<<dim3(3, 4), 256>>>(Wq, Wk, Wv);
    proj_kernel<<<dim3(128, 3), 256>>>(q, k, v);
    vtile_kernel<<<dim3(BB, 32), 64>>>();
    vpre_kernel<<<1, 256>>>();
    attn_kernel<<<332, 256, attn_smem>>>(pad);
    final_kernel<<<BB * TT * HH / 4 / 256, 256>>>(out);
}

// round 7
// speedup vs baseline: 1.7212x; 1.3842x over previous
#include <cuda_runtime.h>
#include <cuda_bf16.h>
#include <cstdint>

#define BB 4
#define TT 2048
#define CC 1024
#define HH 64
#define AST 68   // attn smem row stride (floats)

__device__ float g_Q[BB*TT*HH];
__device__ float g_K[BB*TT*HH];
__device__ float g_V[BB*TT*HH];
__device__ uint32_t g_WpHi[3][HH][CC/2];   // [col][k-pair] packed bf16x2 (low = even k)
__device__ uint32_t g_WpLo[3][HH][CC/2];
__device__ float g_Vtile[BB][32][HH];
__device__ float g_accO[4][BB*TT*HH];
__device__ float g_accL[4][BB*TT];

// pack float2 -> bf16x2 hi + bf16x2 lo (split-bf16)
__device__ __forceinline__ void cvt_pair(float2 f, uint32_t& hi, uint32_t& lo) {
    __nv_bfloat162 h = __float22bfloat162_rn(f);          // .x = f.x (low half)
    hi = *reinterpret_cast<uint32_t*>(&h);
    float h0 = __uint_as_float(hi << 16);
    float h1 = __uint_as_float(hi & 0xffff0000u);
    __nv_bfloat162 l = __float22bfloat162_rn(make_float2(f.x - h0, f.y - h1));
    lo = *reinterpret_cast<uint32_t*>(&l);
}

__device__ __forceinline__ void mma_bf16(float* c, const uint32_t* a, uint32_t b0, uint32_t b1) {
    asm("mma.sync.aligned.m16n8k16.row.col.f32.bf16.bf16.f32 "
        "{%0,%1,%2,%3}, {%4,%5,%6,%7}, {%8,%9}, {%0,%1,%2,%3};"
        : "+f"(c[0]), "+f"(c[1]), "+f"(c[2]), "+f"(c[3])
        : "r"(a[0]), "r"(a[1]), "r"(a[2]), "r"(a[3]), "r"(b0), "r"(b1));
}

// ---------------- W prepack: g_Wp{Hi,Lo}[z][col][j] = split-bf16 of (W[2j][col], W[2j+1][col]) ----
__global__ void wprep_kernel(const float* __restrict__ Wq, const float* __restrict__ Wk,
                             const float* __restrict__ Wv)
{
    int z = blockIdx.x;
    const float* W = (z == 0) ? Wq : (z == 1) ? Wk : Wv;
    int idx = blockIdx.y * 256 + threadIdx.x;     // 0..32767
    int col = idx & 63, j = idx >> 6;
    float w0 = W[(size_t)(2*j) * HH + col];
    float w1 = W[(size_t)(2*j+1) * HH + col];
    uint32_t hi, lo;
    cvt_pair(make_float2(w0, w1), hi, lo);
    g_WpHi[z][col][j] = hi;
    g_WpLo[z][col][j] = lo;
}

// ---------------- Projection: mma.sync bf16x3.  CTA = 128 rows, 4 warps x 32 rows ----------------
__global__ __launch_bounds__(128) void proj_kernel(
    const float* __restrict__ q, const float* __restrict__ k, const float* __restrict__ v)
{
    int z = blockIdx.y;
    const float* X = (z == 0) ? q : (z == 1) ? k : v;
    float* O = (z == 0) ? g_Q : (z == 1) ? g_K : g_V;
    const uint32_t* WH = &g_WpHi[z][0][0];
    const uint32_t* WL = &g_WpLo[z][0][0];

    __shared__ uint32_t sBh[64][68];
    __shared__ uint32_t sBl[64][68];

    int t = threadIdx.x, warp = t >> 5, lane = t & 31;
    int g = lane >> 2, tig = lane & 3;
    int row0 = blockIdx.x * 128 + warp * 32;

    const float* pA[4];
    pA[0] = X + (size_t)(row0 + g)      * CC + 2 * tig;
    pA[1] = X + (size_t)(row0 + g + 8)  * CC + 2 * tig;
    pA[2] = X + (size_t)(row0 + g + 16) * CC + 2 * tig;
    pA[3] = X + (size_t)(row0 + g + 24) * CC + 2 * tig;

    float acc[2][8][4];
#pragma unroll
    for (int mt = 0; mt < 2; mt++)
#pragma unroll
        for (int j = 0; j < 8; j++)
#pragma unroll
            for (int e = 0; e < 4; e++) acc[mt][j][e] = 0.f;

    for (int c = 0; c < 8; c++) {                 // 8 chunks of K=128
        for (int i = t; i < 1024; i += 128) {
            int col = i >> 4, f4 = (i & 15) << 2;
            *(uint4*)&sBh[col][f4] = *(const uint4*)&WH[col * (CC/2) + c * 64 + f4];
            *(uint4*)&sBl[col][f4] = *(const uint4*)&WL[col * (CC/2) + c * 64 + f4];
        }
        __syncthreads();

#pragma unroll
        for (int s = 0; s < 8; s++) {             // k16 steps
            int k0 = c * 128 + s * 16;
            uint32_t ah[2][4], al[2][4];
#pragma unroll
            for (int mt = 0; mt < 2; mt++) {
                float2 f0 = *(const float2*)(pA[mt*2+0] + k0);
                float2 f1 = *(const float2*)(pA[mt*2+1] + k0);
                float2 f2 = *(const float2*)(pA[mt*2+0] + k0 + 8);
                float2 f3 = *(const float2*)(pA[mt*2+1] + k0 + 8);
                cvt_pair(f0, ah[mt][0], al[mt][0]);
                cvt_pair(f1, ah[mt][1], al[mt][1]);
                cvt_pair(f2, ah[mt][2], al[mt][2]);
                cvt_pair(f3, ah[mt][3], al[mt][3]);
            }
#pragma unroll
            for (int j = 0; j < 8; j++) {
                int colr = j * 8 + g;
                uint32_t bh0 = sBh[colr][s*8 + tig],  bh1 = sBh[colr][s*8 + tig + 4];
                uint32_t bl0 = sBl[colr][s*8 + tig],  bl1 = sBl[colr][s*8 + tig + 4];
#pragma unroll
                for (int mt = 0; mt < 2; mt++) {
                    mma_bf16(acc[mt][j], ah[mt], bh0, bh1);
                    mma_bf16(acc[mt][j], ah[mt], bl0, bl1);
                    mma_bf16(acc[mt][j], al[mt], bh0, bh1);
                }
            }
        }
        __syncthreads();
    }

#pragma unroll
    for (int mt = 0; mt < 2; mt++) {
        int r0 = row0 + mt * 16 + g;
#pragma unroll
        for (int j = 0; j < 8; j++) {
            int col = j * 8 + 2 * tig;
            *(float2*)&O[(size_t)r0 * HH + col]       = make_float2(acc[mt][j][0], acc[mt][j][1]);
            *(float2*)&O[(size_t)(r0 + 8) * HH + col] = make_float2(acc[mt][j][2], acc[mt][j][3]);
        }
    }
}

// ---------------- V tile sums (for masked-suffix closed form) ----------------
__global__ void vtile_kernel() {
    int b = blockIdx.x, kt = blockIdx.y, h = threadIdx.x;
    const float* V = g_V + ((size_t)b * TT + kt * 64) * HH;
    float a = 0.f;
#pragma unroll 8
    for (int j = 0; j < 64; j++) a += V[j * HH + h];
    g_Vtile[b][kt][h] = a;
}

// ---------------- Attention: split-KV, fixed exp basis ----------------
// masked weight = expf(1.25e-10) == 1.0f exactly; kept weight = expf(s*0.125).
__global__ __launch_bounds__(256) void attn_kernel(const int* __restrict__ pad)
{
    extern __shared__ float smem[];
    float* sQ = smem;                    // 64 x AST
    float* sK = smem + 64 * AST;
    float* sV = smem + 2 * 64 * AST;
    float* sP = smem + 3 * 64 * AST;

    int u = blockIdx.x;
    int b = u & 3, w = u >> 2;
    int qt = 0, chunk = 0, rem = w;
#pragma unroll 1
    for (int q2 = 31; q2 >= 0; q2--) {
        int kte = q2 + 2; if (kte > 32) kte = 32;
        int s = (kte + 7) >> 3;
        if (rem < s) { qt = q2; chunk = rem; break; }
        rem -= s;
    }
    int kt_end = qt + 2; if (kt_end > 32) kt_end = 32;
    int kt0 = chunk * 8, kt1 = kt0 + 8; if (kt1 > kt_end) kt1 = kt_end;
    bool last = (kt1 == kt_end);
    int qi0 = qt * 64;

    const float* Q = g_Q + (size_t)b * TT * HH;
    const float* K = g_K + (size_t)b * TT * HH;
    const float* V = g_V + (size_t)b * TT * HH;

    int t = threadIdx.x;
    int r = t >> 4, c = t & 15;

#pragma unroll
    for (int i = 0; i < 4; i++) {
        int idx = i * 256 + t;
        int rr = idx >> 4, cc = (idx & 15) << 2;
        *(float4*)&sQ[rr * AST + cc] = *(const float4*)&Q[(size_t)(qi0 + rr) * HH + cc];
    }
    bool padr[4];
#pragma unroll
    for (int m = 0; m < 4; m++) padr[m] = (pad[b * TT + qi0 + r + 16 * m] == 1);

    float4 Oa[4];
    float lp[4];
#pragma unroll
    for (int m = 0; m < 4; m++) { Oa[m] = make_float4(0.f,0.f,0.f,0.f); lp[m] = 0.f; }

#pragma unroll 1
    for (int kt = kt0; kt < kt1; kt++) {
        int kj0 = kt * 64;
        __syncthreads();
#pragma unroll
        for (int i = 0; i < 4; i++) {
            int idx = i * 256 + t;
            int rr = idx >> 4, cc = (idx & 15) << 2;
            *(float4*)&sK[rr * AST + cc] = *(const float4*)&K[(size_t)(kj0 + rr) * HH + cc];
            *(float4*)&sV[rr * AST + cc] = *(const float4*)&V[(size_t)(kj0 + rr) * HH + cc];
        }
        __syncthreads();

        float s[4][4];
#pragma unroll
        for (int m = 0; m < 4; m++)
#pragma unroll
            for (int n = 0; n < 4; n++) s[m][n] = 0.f;
#pragma unroll
        for (int kk = 0; kk < 64; kk += 4) {
            float4 qv[4], kv[4];
#pragma unroll
            for (int m = 0; m < 4; m++) qv[m] = *(float4*)&sQ[(r + 16 * m) * AST + kk];
#pragma unroll
            for (int n = 0; n < 4; n++) kv[n] = *(float4*)&sK[(c + 16 * n) * AST + kk];
#pragma unroll
            for (int m = 0; m < 4; m++)
#pragma unroll
                for (int n = 0; n < 4; n++)
                    s[m][n] += qv[m].x*kv[n].x + qv[m].y*kv[n].y
                             + qv[m].z*kv[n].z + qv[m].w*kv[n].w;
        }
#pragma unroll
        for (int m = 0; m < 4; m++) {
            int row = qi0 + r + 16 * m;
#pragma unroll
            for (int n = 0; n < 4; n++) {
                int col = kj0 + c + 16 * n;
                float wv = ((col <= row + 1) && !padr[m]) ? __expf(s[m][n] * 0.125f) : 1.0f;
                lp[m] += wv;
                sP[(r + 16 * m) * AST + c + 16 * n] = wv;
            }
        }
        __syncthreads();
#pragma unroll
        for (int kk = 0; kk < 64; kk += 4) {
            float4 pv[4], vv[4];
#pragma unroll
            for (int m = 0; m < 4; m++) pv[m] = *(float4*)&sP[(r + 16 * m) * AST + kk];
#pragma unroll
            for (int d = 0; d < 4; d++) vv[d] = *(float4*)&sV[(kk + d) * AST + (c << 2)];
#pragma unroll
            for (int m = 0; m < 4; m++) {
                Oa[m].x += pv[m].x*vv[0].x + pv[m].y*vv[1].x + pv[m].z*vv[2].x + pv[m].w*vv[3].x;
                Oa[m].y += pv[m].x*vv[0].y + pv[m].y*vv[1].y + pv[m].z*vv[2].y + pv[m].w*vv[3].y;
                Oa[m].z += pv[m].x*vv[0].z + pv[m].y*vv[1].z + pv[m].z*vv[2].z + pv[m].w*vv[3].z;
                Oa[m].w += pv[m].x*vv[0].w + pv[m].y*vv[1].w + pv[m].z*vv[2].w + pv[m].w*vv[3].w;
            }
        }
    }

#pragma unroll
    for (int m = 0; m < 4; m++)
#pragma unroll
        for (int o = 1; o < 16; o <<= 1)
            lp[m] += __shfl_xor_sync(0xffffffffu, lp[m], o, 16);

    // fully-masked suffix (weight exactly 1.0 each): count + V tile-sum reads
    if (last && kt_end < 32) {
        float4 suf = make_float4(0.f, 0.f, 0.f, 0.f);
#pragma unroll 1
        for (int kt2 = kt_end; kt2 < 32; kt2++) {
            float4 tv = *(const float4*)&g_Vtile[b][kt2][c << 2];
            suf.x += tv.x; suf.y += tv.y; suf.z += tv.z; suf.w += tv.w;
        }
        float cnt = (float)(TT - kt_end * 64);
#pragma unroll
        for (int m = 0; m < 4; m++) {
            Oa[m].x += suf.x; Oa[m].y += suf.y; Oa[m].z += suf.z; Oa[m].w += suf.w;
            lp[m] += cnt;
        }
    }

#pragma unroll
    for (int m = 0; m < 4; m++) {
        size_t row = (size_t)b * TT + qi0 + r + 16 * m;
        *(float4*)&g_accO[chunk][row * HH + (c << 2)] = Oa[m];
        if (c == 0) g_accL[chunk][row] = lp[m];
    }
}

// ---------------- combine partials, divide ----------------
__global__ void final_kernel(float* __restrict__ out)
{
    int idx = blockIdx.x * 256 + threadIdx.x;
    int row = idx >> 4;
    int qt = (row & (TT - 1)) >> 6;
    int kte = qt + 2; if (kte > 32) kte = 32;
    int ns = (kte + 7) >> 3;
    float l = 0.f;
    float4 o = make_float4(0.f,0.f,0.f,0.f);
#pragma unroll 1
    for (int s = 0; s < ns; s++) {
        l += g_accL[s][row];
        float4 p = ((const float4*)g_accO[s])[idx];
        o.x += p.x; o.y += p.y; o.z += p.z; o.w += p.w;
    }
    float inv = 1.f / l;
    ((float4*)out)[idx] = make_float4(o.x*inv, o.y*inv, o.z*inv, o.w*inv);
}

extern "C" void kernel_launch(void* const* d_in, const int* in_sizes, int n_in,
                              void* d_out, int out_size)
{
    const float* q  = (const float*)d_in[0];
    const float* k  = (const float*)d_in[1];
    const float* v  = (const float*)d_in[2];
    const float* Wq = (const float*)d_in[3];
    const float* Wk = (const float*)d_in[4];
    const float* Wv = (const float*)d_in[5];
    const int* pad  = (const int*)d_in[6];
    float* out = (float*)d_out;

    const int attn_smem = 4 * 64 * AST * (int)sizeof(float);   // 69,632 B
    cudaFuncSetAttribute(attn_kernel, cudaFuncAttributeMaxDynamicSharedMemorySize, attn_smem);

    wprep_kernel<<<dim3(3, 128), 256>>>(Wq, Wk, Wv);
    proj_kernel<<<dim3(64, 3), 128>>>(q, k, v);
    vtile_kernel<<<dim3(BB, 32), 64>>>();
    attn_kernel<<<332, 256, attn_smem>>>(pad);
    final_kernel<<<BB * TT * HH / 4 / 256, 256>>>(out);
}

// round 9
// speedup vs baseline: 2.5078x; 1.4570x over previous
#include <cuda_runtime.h>
#include <cuda_bf16.h>
#include <cstdint>

#define BB 4
#define TT 2048
#define CC 1024
#define HH 64

__device__ float g_V[BB*TT*HH];                    // fp32 V (suffix sums)
__device__ uint32_t g_WpHi[3][HH][CC/2];
__device__ uint32_t g_WpLo[3][HH][CC/2];
__device__ uint32_t g_OHi[3][BB*TT*HH/2];          // projected Q/K/V, packed bf16x2 hi
__device__ uint32_t g_OLo[3][BB*TT*HH/2];          // lo
__device__ float g_Vtile[BB][32][HH];
__device__ float g_accO[4][BB*TT*HH];
__device__ float g_accL[4][BB*TT];

// pack float2 -> bf16x2 hi + bf16x2 lo (split-bf16); low 16 bits = .x
__device__ __forceinline__ void cvt_pair(float2 f, uint32_t& hi, uint32_t& lo) {
    __nv_bfloat162 h = __float22bfloat162_rn(f);
    hi = *reinterpret_cast<uint32_t*>(&h);
    float h0 = __uint_as_float(hi << 16);
    float h1 = __uint_as_float(hi & 0xffff0000u);
    __nv_bfloat162 l = __float22bfloat162_rn(make_float2(f.x - h0, f.y - h1));
    lo = *reinterpret_cast<uint32_t*>(&l);
}

__device__ __forceinline__ void mma_bf16(float* c, const uint32_t* a, uint32_t b0, uint32_t b1) {
    asm("mma.sync.aligned.m16n8k16.row.col.f32.bf16.bf16.f32 "
        "{%0,%1,%2,%3}, {%4,%5,%6,%7}, {%8,%9}, {%0,%1,%2,%3};"
        : "+f"(c[0]), "+f"(c[1]), "+f"(c[2]), "+f"(c[3])
        : "r"(a[0]), "r"(a[1]), "r"(a[2]), "r"(a[3]), "r"(b0), "r"(b1));
}
__device__ __forceinline__ void ldsm4(uint32_t& r0, uint32_t& r1, uint32_t& r2, uint32_t& r3, uint32_t a) {
    asm volatile("ldmatrix.sync.aligned.m8n8.x4.shared.b16 {%0,%1,%2,%3}, [%4];"
                 : "=r"(r0), "=r"(r1), "=r"(r2), "=r"(r3) : "r"(a));
}
__device__ __forceinline__ void ldsm4t(uint32_t& r0, uint32_t& r1, uint32_t& r2, uint32_t& r3, uint32_t a) {
    asm volatile("ldmatrix.sync.aligned.m8n8.x4.trans.shared.b16 {%0,%1,%2,%3}, [%4];"
                 : "=r"(r0), "=r"(r1), "=r"(r2), "=r"(r3) : "r"(a));
}
__device__ __forceinline__ uint32_t smem_u32(const void* p) {
    uint32_t a;
    asm("{ .reg .u64 t; cvta.to.shared.u64 t, %1; cvt.u32.u64 %0, t; }" : "=r"(a) : "l"(p));
    return a;
}

// ---------------- W prepack ----------------
__global__ void wprep_kernel(const float* __restrict__ Wq, const float* __restrict__ Wk,
                             const float* __restrict__ Wv)
{
    int z = blockIdx.x;
    const float* W = (z == 0) ? Wq : (z == 1) ? Wk : Wv;
    int idx = blockIdx.y * 256 + threadIdx.x;
    int col = idx & 63, j = idx >> 6;
    uint32_t hi, lo;
    cvt_pair(make_float2(W[(size_t)(2*j) * HH + col], W[(size_t)(2*j+1) * HH + col]), hi, lo);
    g_WpHi[z][col][j] = hi;
    g_WpLo[z][col][j] = lo;
}

// ---------------- Projection: mma.sync bf16x3; epilogue emits bf16 hi/lo pairs ----------------
__global__ __launch_bounds__(128) void proj_kernel(
    const float* __restrict__ q, const float* __restrict__ k, const float* __restrict__ v)
{
    int z = blockIdx.y;
    const float* X = (z == 0) ? q : (z == 1) ? k : v;
    const uint32_t* WH = &g_WpHi[z][0][0];
    const uint32_t* WL = &g_WpLo[z][0][0];

    __shared__ uint32_t sBh[64][68];
    __shared__ uint32_t sBl[64][68];

    int t = threadIdx.x, warp = t >> 5, lane = t & 31;
    int g = lane >> 2, tig = lane & 3;
    int row0 = blockIdx.x * 128 + warp * 32;

    const float* pA[4];
    pA[0] = X + (size_t)(row0 + g)      * CC + 2 * tig;
    pA[1] = X + (size_t)(row0 + g + 8)  * CC + 2 * tig;
    pA[2] = X + (size_t)(row0 + g + 16) * CC + 2 * tig;
    pA[3] = X + (size_t)(row0 + g + 24) * CC + 2 * tig;

    float acc[2][8][4];
#pragma unroll
    for (int mt = 0; mt < 2; mt++)
#pragma unroll
        for (int j = 0; j < 8; j++)
#pragma unroll
            for (int e = 0; e < 4; e++) acc[mt][j][e] = 0.f;

    for (int c = 0; c < 8; c++) {
        for (int i = t; i < 1024; i += 128) {
            int col = i >> 4, f4 = (i & 15) << 2;
            *(uint4*)&sBh[col][f4] = *(const uint4*)&WH[col * (CC/2) + c * 64 + f4];
            *(uint4*)&sBl[col][f4] = *(const uint4*)&WL[col * (CC/2) + c * 64 + f4];
        }
        __syncthreads();
#pragma unroll
        for (int s = 0; s < 8; s++) {
            int k0 = c * 128 + s * 16;
            uint32_t ah[2][4], al[2][4];
#pragma unroll
            for (int mt = 0; mt < 2; mt++) {
                cvt_pair(*(const float2*)(pA[mt*2+0] + k0),     ah[mt][0], al[mt][0]);
                cvt_pair(*(const float2*)(pA[mt*2+1] + k0),     ah[mt][1], al[mt][1]);
                cvt_pair(*(const float2*)(pA[mt*2+0] + k0 + 8), ah[mt][2], al[mt][2]);
                cvt_pair(*(const float2*)(pA[mt*2+1] + k0 + 8), ah[mt][3], al[mt][3]);
            }
#pragma unroll
            for (int j = 0; j < 8; j++) {
                int colr = j * 8 + g;
                uint32_t bh0 = sBh[colr][s*8 + tig], bh1 = sBh[colr][s*8 + tig + 4];
                uint32_t bl0 = sBl[colr][s*8 + tig], bl1 = sBl[colr][s*8 + tig + 4];
#pragma unroll
                for (int mt = 0; mt < 2; mt++) {
                    mma_bf16(acc[mt][j], ah[mt], bh0, bh1);
                    mma_bf16(acc[mt][j], ah[mt], bl0, bl1);
                    mma_bf16(acc[mt][j], al[mt], bh0, bh1);
                }
            }
        }
        __syncthreads();
    }

    uint32_t* OH = g_OHi[z];
    uint32_t* OL = g_OLo[z];
#pragma unroll
    for (int mt = 0; mt < 2; mt++) {
        int r0 = row0 + mt * 16 + g;
#pragma unroll
        for (int j = 0; j < 8; j++) {
            int col = j * 8 + 2 * tig;
            float2 fa = make_float2(acc[mt][j][0], acc[mt][j][1]);
            float2 fb = make_float2(acc[mt][j][2], acc[mt][j][3]);
            uint32_t hi, lo;
            cvt_pair(fa, hi, lo);
            OH[((size_t)r0 * HH + col) >> 1] = hi;
            OL[((size_t)r0 * HH + col) >> 1] = lo;
            cvt_pair(fb, hi, lo);
            OH[((size_t)(r0 + 8) * HH + col) >> 1] = hi;
            OL[((size_t)(r0 + 8) * HH + col) >> 1] = lo;
            if (z == 2) {
                *(float2*)&g_V[(size_t)r0 * HH + col] = fa;
                *(float2*)&g_V[(size_t)(r0 + 8) * HH + col] = fb;
            }
        }
    }
}

// ---------------- V tile sums ----------------
__global__ void vtile_kernel() {
    int b = blockIdx.x, kt = blockIdx.y, h = threadIdx.x;
    const float* V = g_V + ((size_t)b * TT + kt * 64) * HH;
    float a = 0.f;
#pragma unroll 8
    for (int j = 0; j < 64; j++) a += V[j * HH + h];
    g_Vtile[b][kt][h] = a;
}

// ---------------- Attention: tensor-core flash, split-KV, fixed exp basis ----------------
#define SROW 72   // smem tile row stride in bf16 (144 B)
__global__ __launch_bounds__(128) void attn_kernel(const int* __restrict__ pad)
{
    extern __shared__ char dyn[];
    uint32_t base = smem_u32(dyn);
    const uint32_t uQh = base, uQl = base + 9216;
    const uint32_t uKh = base + 18432, uKl = base + 27648;
    const uint32_t uVh = base + 36864, uVl = base + 46080;
    float* sSuf = (float*)(dyn + 55296);

    int u = blockIdx.x;
    int b = u & 3, w = u >> 2;
    int qt = 0, chunk = 0, rem = w;
#pragma unroll 1
    for (int q2 = 31; q2 >= 0; q2--) {
        int kte = q2 + 2; if (kte > 32) kte = 32;
        int s = (kte + 7) >> 3;
        if (rem < s) { qt = q2; chunk = rem; break; }
        rem -= s;
    }
    int kt_end = qt + 2; if (kt_end > 32) kt_end = 32;
    int kt0 = chunk * 8, kt1 = kt0 + 8; if (kt1 > kt_end) kt1 = kt_end;
    bool last = (kt1 == kt_end);
    int qi0 = qt * 64;

    const uint4* QH = (const uint4*)g_OHi[0];
    const uint4* QL = (const uint4*)g_OLo[0];
    const uint4* KH = (const uint4*)g_OHi[1];
    const uint4* KL = (const uint4*)g_OLo[1];
    const uint4* VH = (const uint4*)g_OHi[2];
    const uint4* VL = (const uint4*)g_OLo[2];

    int t = threadIdx.x, warp = t >> 5, lane = t & 31;
    int g = lane >> 2, tig = lane & 3;
    int r0 = qi0 + warp * 16 + g, r1 = r0 + 8;
    bool pad0 = (pad[b * TT + r0] == 1);
    bool pad1 = (pad[b * TT + r1] == 1);

    // per-lane ldmatrix row/col roles
    int rowA = (lane & 8) + (lane & 7), colA8 = (lane & 16) >> 1;   // A & V(trans) pattern
    int rowK = ((lane & 16) >> 1) + (lane & 7), colK8 = (lane & 8); // K(B) pattern

    // stage Q (hi/lo) -> smem
    for (int i = t; i < 512; i += 128) {
        int rr = i >> 3, c = i & 7;
        size_t src = (size_t)(b * TT + qi0 + rr) * 8 + c;
        *(uint4*)(dyn + (uQh - base) + rr * 144 + c * 16) = QH[src];
        *(uint4*)(dyn + (uQl - base) + rr * 144 + c * 16) = QL[src];
    }
    __syncthreads();

    // Q fragments (held in registers for the whole unit)
    uint32_t qh[4][4], ql[4][4];
#pragma unroll
    for (int j = 0; j < 4; j++) {
        uint32_t off = (uint32_t)((warp * 16 + rowA) * SROW + j * 16 + colA8) * 2;
        ldsm4(qh[j][0], qh[j][1], qh[j][2], qh[j][3], uQh + off);
        ldsm4(ql[j][0], ql[j][1], ql[j][2], ql[j][3], uQl + off);
    }

    float Oacc[8][4];
#pragma unroll
    for (int nt = 0; nt < 8; nt++)
#pragma unroll
        for (int e = 0; e < 4; e++) Oacc[nt][e] = 0.f;
    float lp0 = 0.f, lp1 = 0.f;

#pragma unroll 1
    for (int kt = kt0; kt < kt1; kt++) {
        int kj0 = kt * 64;
        __syncthreads();
        for (int i = t; i < 512; i += 128) {
            int rr = i >> 3, c = i & 7;
            size_t src = (size_t)(b * TT + kj0 + rr) * 8 + c;
            int d = rr * 144 + c * 16;
            *(uint4*)(dyn + (uKh - base) + d) = KH[src];
            *(uint4*)(dyn + (uKl - base) + d) = KL[src];
            *(uint4*)(dyn + (uVh - base) + d) = VH[src];
            *(uint4*)(dyn + (uVl - base) + d) = VL[src];
        }
        __syncthreads();

        // S = Q K^T (split-bf16, 3 products)
        float S[8][4];
#pragma unroll
        for (int nt = 0; nt < 8; nt++)
#pragma unroll
            for (int e = 0; e < 4; e++) S[nt][e] = 0.f;
#pragma unroll
        for (int j = 0; j < 4; j++) {
#pragma unroll
            for (int np = 0; np < 4; np++) {
                uint32_t off = (uint32_t)((np * 16 + rowK) * SROW + j * 16 + colK8) * 2;
                uint32_t kh0, kh1, kh2, kh3, kl0, kl1, kl2, kl3;
                ldsm4(kh0, kh1, kh2, kh3, uKh + off);
                ldsm4(kl0, kl1, kl2, kl3, uKl + off);
                mma_bf16(S[2*np],   qh[j], kh0, kh1);
                mma_bf16(S[2*np],   qh[j], kl0, kl1);
                mma_bf16(S[2*np],   ql[j], kh0, kh1);
                mma_bf16(S[2*np+1], qh[j], kh2, kh3);
                mma_bf16(S[2*np+1], qh[j], kl2, kl3);
                mma_bf16(S[2*np+1], ql[j], kh2, kh3);
            }
        }

        // weights: masked -> exactly 1.0; kept -> exp(s/8)
#pragma unroll
        for (int nt = 0; nt < 8; nt++) {
            int col0 = kj0 + nt * 8 + 2 * tig;
            S[nt][0] = (!pad0 && col0     <= r0 + 1) ? __expf(S[nt][0] * 0.125f) : 1.0f;
            S[nt][1] = (!pad0 && col0 + 1 <= r0 + 1) ? __expf(S[nt][1] * 0.125f) : 1.0f;
            S[nt][2] = (!pad1 && col0     <= r1 + 1) ? __expf(S[nt][2] * 0.125f) : 1.0f;
            S[nt][3] = (!pad1 && col0 + 1 <= r1 + 1) ? __expf(S[nt][3] * 0.125f) : 1.0f;
            lp0 += S[nt][0] + S[nt][1];
            lp1 += S[nt][2] + S[nt][3];
        }

        // O += P V (P re-split to bf16 hi/lo A-fragments; V via ldmatrix.trans)
#pragma unroll
        for (int j = 0; j < 4; j++) {
            uint32_t ah[4], al[4];
            cvt_pair(make_float2(S[2*j][0],   S[2*j][1]),   ah[0], al[0]);
            cvt_pair(make_float2(S[2*j][2],   S[2*j][3]),   ah[1], al[1]);
            cvt_pair(make_float2(S[2*j+1][0], S[2*j+1][1]), ah[2], al[2]);
            cvt_pair(make_float2(S[2*j+1][2], S[2*j+1][3]), ah[3], al[3]);
#pragma unroll
            for (int np = 0; np < 4; np++) {
                uint32_t off = (uint32_t)((j * 16 + rowA) * SROW + np * 16 + colA8) * 2;
                uint32_t vh0, vh1, vh2, vh3, vl0, vl1, vl2, vl3;
                ldsm4t(vh0, vh1, vh2, vh3, uVh + off);
                ldsm4t(vl0, vl1, vl2, vl3, uVl + off);
                mma_bf16(Oacc[2*np],   ah, vh0, vh1);
                mma_bf16(Oacc[2*np],   ah, vl0, vl1);
                mma_bf16(Oacc[2*np],   al, vh0, vh1);
                mma_bf16(Oacc[2*np+1], ah, vh2, vh3);
                mma_bf16(Oacc[2*np+1], ah, vl2, vl3);
                mma_bf16(Oacc[2*np+1], al, vh2, vh3);
            }
        }
    }

    // l row-sums across the 4 lanes sharing each row
    lp0 += __shfl_xor_sync(0xffffffffu, lp0, 1, 4);
    lp0 += __shfl_xor_sync(0xffffffffu, lp0, 2, 4);
    lp1 += __shfl_xor_sync(0xffffffffu, lp1, 1, 4);
    lp1 += __shfl_xor_sync(0xffffffffu, lp1, 2, 4);

    // fully-masked suffix (weight exactly 1.0): V column sums + count
    if (last && kt_end < 32) {
        __syncthreads();
        if (t < 64) {
            float a = 0.f;
            for (int kt2 = kt_end; kt2 < 32; kt2++) a += g_Vtile[b][kt2][t];
            sSuf[t] = a;
        }
        __syncthreads();
        float cnt = (float)(TT - kt_end * 64);
        lp0 += cnt; lp1 += cnt;
#pragma unroll
        for (int nt = 0; nt < 8; nt++) {
            int col = nt * 8 + 2 * tig;
            float s0 = sSuf[col], s1 = sSuf[col + 1];
            Oacc[nt][0] += s0; Oacc[nt][1] += s1;
            Oacc[nt][2] += s0; Oacc[nt][3] += s1;
        }
    }

    // store partials
    if (tig == 0) {
        g_accL[chunk][(size_t)b * TT + r0] = lp0;
        g_accL[chunk][(size_t)b * TT + r1] = lp1;
    }
#pragma unroll
    for (int nt = 0; nt < 8; nt++) {
        int col = nt * 8 + 2 * tig;
        *(float2*)&g_accO[chunk][((size_t)b * TT + r0) * HH + col] =
            make_float2(Oacc[nt][0], Oacc[nt][1]);
        *(float2*)&g_accO[chunk][((size_t)b * TT + r1) * HH + col] =
            make_float2(Oacc[nt][2], Oacc[nt][3]);
    }
}

// ---------------- combine partials, divide ----------------
__global__ void final_kernel(float* __restrict__ out)
{
    int idx = blockIdx.x * 256 + threadIdx.x;
    int row = idx >> 4;
    int qt = (row & (TT - 1)) >> 6;
    int kte = qt + 2; if (kte > 32) kte = 32;
    int ns = (kte + 7) >> 3;
    float l = 0.f;
    float4 o = make_float4(0.f, 0.f, 0.f, 0.f);
#pragma unroll 1
    for (int s = 0; s < ns; s++) {
        l += g_accL[s][row];
        float4 p = ((const float4*)g_accO[s])[idx];
        o.x += p.x; o.y += p.y; o.z += p.z; o.w += p.w;
    }
    float inv = 1.f / l;
    ((float4*)out)[idx] = make_float4(o.x*inv, o.y*inv, o.z*inv, o.w*inv);
}

extern "C" void kernel_launch(void* const* d_in, const int* in_sizes, int n_in,
                              void* d_out, int out_size)
{
    const float* q  = (const float*)d_in[0];
    const float* k  = (const float*)d_in[1];
    const float* v  = (const float*)d_in[2];
    const float* Wq = (const float*)d_in[3];
    const float* Wk = (const float*)d_in[4];
    const float* Wv = (const float*)d_in[5];
    const int* pad  = (const int*)d_in[6];
    float* out = (float*)d_out;

    const int attn_smem = 55296 + 256;   // 6 bf16 tiles @144B-stride + suffix
    cudaFuncSetAttribute(attn_kernel, cudaFuncAttributeMaxDynamicSharedMemorySize, attn_smem);

    wprep_kernel<<<dim3(3, 128), 256>>>(Wq, Wk, Wv);
    proj_kernel<<<dim3(64, 3), 128>>>(q, k, v);
    vtile_kernel<<<dim3(BB, 32), 64>>>();
    attn_kernel<<<332, 128, attn_smem>>>(pad);
    final_kernel<<<BB * TT * HH / 4 / 256, 256>>>(out);
}

// round 10
// speedup vs baseline: 2.5965x; 1.0354x over previous
#include <cuda_runtime.h>
#include <cuda_bf16.h>
#include <cstdint>

#define BB 4
#define TT 2048
#define CC 1024
#define HH 64

__device__ uint32_t g_WpHi[3][HH][CC/2];
__device__ uint32_t g_WpLo[3][HH][CC/2];
__device__ uint32_t g_OHi[3][BB*TT*HH/2];          // projected Q/K/V, packed bf16x2 hi
__device__ uint32_t g_OLo[3][BB*TT*HH/2];          // lo
__device__ float g_Vtile[BB][32][HH];
__device__ float g_accO[8][BB*TT*HH];
__device__ float g_accL[8][BB*TT];

// pack float2 -> bf16x2 hi + bf16x2 lo (split-bf16); low 16 bits = .x
__device__ __forceinline__ void cvt_pair(float2 f, uint32_t& hi, uint32_t& lo) {
    __nv_bfloat162 h = __float22bfloat162_rn(f);
    hi = *reinterpret_cast<uint32_t*>(&h);
    float h0 = __uint_as_float(hi << 16);
    float h1 = __uint_as_float(hi & 0xffff0000u);
    __nv_bfloat162 l = __float22bfloat162_rn(make_float2(f.x - h0, f.y - h1));
    lo = *reinterpret_cast<uint32_t*>(&l);
}

__device__ __forceinline__ void mma_bf16(float* c, const uint32_t* a, uint32_t b0, uint32_t b1) {
    asm("mma.sync.aligned.m16n8k16.row.col.f32.bf16.bf16.f32 "
        "{%0,%1,%2,%3}, {%4,%5,%6,%7}, {%8,%9}, {%0,%1,%2,%3};"
        : "+f"(c[0]), "+f"(c[1]), "+f"(c[2]), "+f"(c[3])
        : "r"(a[0]), "r"(a[1]), "r"(a[2]), "r"(a[3]), "r"(b0), "r"(b1));
}
__device__ __forceinline__ void ldsm4(uint32_t& r0, uint32_t& r1, uint32_t& r2, uint32_t& r3, uint32_t a) {
    asm volatile("ldmatrix.sync.aligned.m8n8.x4.shared.b16 {%0,%1,%2,%3}, [%4];"
                 : "=r"(r0), "=r"(r1), "=r"(r2), "=r"(r3) : "r"(a));
}
__device__ __forceinline__ void ldsm4t(uint32_t& r0, uint32_t& r1, uint32_t& r2, uint32_t& r3, uint32_t a) {
    asm volatile("ldmatrix.sync.aligned.m8n8.x4.trans.shared.b16 {%0,%1,%2,%3}, [%4];"
                 : "=r"(r0), "=r"(r1), "=r"(r2), "=r"(r3) : "r"(a));
}
__device__ __forceinline__ uint32_t smem_u32(const void* p) {
    uint32_t a;
    asm("{ .reg .u64 t; cvta.to.shared.u64 t, %1; cvt.u32.u64 %0, t; }" : "=r"(a) : "l"(p));
    return a;
}
__device__ __forceinline__ void cp16(uint32_t dst, const void* src) {
    asm volatile("cp.async.cg.shared.global [%0], [%1], 16;" :: "r"(dst), "l"(src));
}
#define CP_COMMIT() asm volatile("cp.async.commit_group;" ::: "memory")
#define CP_WAIT1()  asm volatile("cp.async.wait_group 1;" ::: "memory")
#define CP_WAIT0()  asm volatile("cp.async.wait_group 0;" ::: "memory")

// ---------------- W prepack ----------------
__global__ void wprep_kernel(const float* __restrict__ Wq, const float* __restrict__ Wk,
                             const float* __restrict__ Wv)
{
    int z = blockIdx.x;
    const float* W = (z == 0) ? Wq : (z == 1) ? Wk : Wv;
    int idx = blockIdx.y * 256 + threadIdx.x;
    int col = idx & 63, j = idx >> 6;
    uint32_t hi, lo;
    cvt_pair(make_float2(W[(size_t)(2*j) * HH + col], W[(size_t)(2*j+1) * HH + col]), hi, lo);
    g_WpHi[z][col][j] = hi;
    g_WpLo[z][col][j] = lo;
}

// ---------------- Projection: mma.sync bf16x3; epilogue emits bf16 hi/lo + V tile sums ----------
__global__ __launch_bounds__(128) void proj_kernel(
    const float* __restrict__ q, const float* __restrict__ k, const float* __restrict__ v)
{
    int z = blockIdx.y;
    const float* X = (z == 0) ? q : (z == 1) ? k : v;
    const uint32_t* WH = &g_WpHi[z][0][0];
    const uint32_t* WL = &g_WpLo[z][0][0];

    __shared__ uint32_t sBh[64][68];
    __shared__ uint32_t sBl[64][68];
    __shared__ float sVs[4][64];

    int t = threadIdx.x, warp = t >> 5, lane = t & 31;
    int g = lane >> 2, tig = lane & 3;
    int rowC = blockIdx.x * 128;
    int row0 = rowC + warp * 32;

    const float* pA[4];
    pA[0] = X + (size_t)(row0 + g)      * CC + 2 * tig;
    pA[1] = X + (size_t)(row0 + g + 8)  * CC + 2 * tig;
    pA[2] = X + (size_t)(row0 + g + 16) * CC + 2 * tig;
    pA[3] = X + (size_t)(row0 + g + 24) * CC + 2 * tig;

    float acc[2][8][4];
#pragma unroll
    for (int mt = 0; mt < 2; mt++)
#pragma unroll
        for (int j = 0; j < 8; j++)
#pragma unroll
            for (int e = 0; e < 4; e++) acc[mt][j][e] = 0.f;

    for (int c = 0; c < 8; c++) {
        for (int i = t; i < 1024; i += 128) {
            int col = i >> 4, f4 = (i & 15) << 2;
            *(uint4*)&sBh[col][f4] = *(const uint4*)&WH[col * (CC/2) + c * 64 + f4];
            *(uint4*)&sBl[col][f4] = *(const uint4*)&WL[col * (CC/2) + c * 64 + f4];
        }
        __syncthreads();
#pragma unroll
        for (int s = 0; s < 8; s++) {
            int k0 = c * 128 + s * 16;
            uint32_t ah[2][4], al[2][4];
#pragma unroll
            for (int mt = 0; mt < 2; mt++) {
                cvt_pair(*(const float2*)(pA[mt*2+0] + k0),     ah[mt][0], al[mt][0]);
                cvt_pair(*(const float2*)(pA[mt*2+1] + k0),     ah[mt][1], al[mt][1]);
                cvt_pair(*(const float2*)(pA[mt*2+0] + k0 + 8), ah[mt][2], al[mt][2]);
                cvt_pair(*(const float2*)(pA[mt*2+1] + k0 + 8), ah[mt][3], al[mt][3]);
            }
#pragma unroll
            for (int j = 0; j < 8; j++) {
                int colr = j * 8 + g;
                uint32_t bh0 = sBh[colr][s*8 + tig], bh1 = sBh[colr][s*8 + tig + 4];
                uint32_t bl0 = sBl[colr][s*8 + tig], bl1 = sBl[colr][s*8 + tig + 4];
#pragma unroll
                for (int mt = 0; mt < 2; mt++) {
                    mma_bf16(acc[mt][j], ah[mt], bh0, bh1);
                    mma_bf16(acc[mt][j], ah[mt], bl0, bl1);
                    mma_bf16(acc[mt][j], al[mt], bh0, bh1);
                }
            }
        }
        __syncthreads();
    }

    uint32_t* OH = g_OHi[z];
    uint32_t* OL = g_OLo[z];
#pragma unroll
    for (int mt = 0; mt < 2; mt++) {
        int r0 = row0 + mt * 16 + g;
#pragma unroll
        for (int j = 0; j < 8; j++) {
            int col = j * 8 + 2 * tig;
            uint32_t hi, lo;
            cvt_pair(make_float2(acc[mt][j][0], acc[mt][j][1]), hi, lo);
            OH[((size_t)r0 * HH + col) >> 1] = hi;
            OL[((size_t)r0 * HH + col) >> 1] = lo;
            cvt_pair(make_float2(acc[mt][j][2], acc[mt][j][3]), hi, lo);
            OH[((size_t)(r0 + 8) * HH + col) >> 1] = hi;
            OL[((size_t)(r0 + 8) * HH + col) >> 1] = lo;
        }
    }

    // V tile column sums (this CTA owns exactly two 64-row tiles)
    if (z == 2) {
        float cs0[8], cs1[8];
#pragma unroll
        for (int j = 0; j < 8; j++) {
            cs0[j] = acc[0][j][0] + acc[0][j][2] + acc[1][j][0] + acc[1][j][2];
            cs1[j] = acc[0][j][1] + acc[0][j][3] + acc[1][j][1] + acc[1][j][3];
        }
#pragma unroll
        for (int off = 4; off < 32; off <<= 1)
#pragma unroll
            for (int j = 0; j < 8; j++) {
                cs0[j] += __shfl_xor_sync(0xffffffffu, cs0[j], off);
                cs1[j] += __shfl_xor_sync(0xffffffffu, cs1[j], off);
            }
        if (lane < 4) {
#pragma unroll
            for (int j = 0; j < 8; j++) {
                sVs[warp][j * 8 + 2 * lane] = cs0[j];
                sVs[warp][j * 8 + 2 * lane + 1] = cs1[j];
            }
        }
        __syncthreads();
        int b2 = rowC >> 11, tb = (rowC & 2047) >> 6;
        if (t < 64)       g_Vtile[b2][tb][t]          = sVs[0][t] + sVs[1][t];
        else if (t < 128) g_Vtile[b2][tb + 1][t - 64] = sVs[2][t - 64] + sVs[3][t - 64];
    }
}

// ---------------- Attention: tensor-core flash, split-KV (4 tiles), cp.async pipeline -----------
#define SROW 72   // smem tile row stride in bf16 (144 B)
__global__ __launch_bounds__(128) void attn_kernel(const int* __restrict__ pad)
{
    extern __shared__ char dyn[];
    uint32_t base = smem_u32(dyn);
    const uint32_t uQh = base, uQl = base + 9216;
    const uint32_t bufBase = base + 18432;            // + buf*36864; Kh/Kl/Vh/Vl at +0/9216/18432/27648
    float* sSuf = (float*)(dyn + 92160);

    int u = blockIdx.x;
    int b = u & 3, w = u >> 2;
    int qt = 0, chunk = 0, rem = w;
#pragma unroll 1
    for (int q2 = 31; q2 >= 0; q2--) {
        int kte = q2 + 2; if (kte > 32) kte = 32;
        int s = (kte + 3) >> 2;
        if (rem < s) { qt = q2; chunk = rem; break; }
        rem -= s;
    }
    int kt_end = qt + 2; if (kt_end > 32) kt_end = 32;
    int kt0 = chunk * 4, kt1 = kt0 + 4; if (kt1 > kt_end) kt1 = kt_end;
    bool last = (kt1 == kt_end);
    int qi0 = qt * 64;

    const uint4* QH = (const uint4*)g_OHi[0];
    const uint4* QL = (const uint4*)g_OLo[0];
    const uint4* KH = (const uint4*)g_OHi[1];
    const uint4* KL = (const uint4*)g_OLo[1];
    const uint4* VH = (const uint4*)g_OHi[2];
    const uint4* VL = (const uint4*)g_OLo[2];

    int t = threadIdx.x, warp = t >> 5, lane = t & 31;
    int g = lane >> 2, tig = lane & 3;
    int r0 = qi0 + warp * 16 + g, r1 = r0 + 8;
    bool pad0 = (pad[b * TT + r0] == 1);
    bool pad1 = (pad[b * TT + r1] == 1);

    int rowA = (lane & 8) + (lane & 7), colA8 = (lane & 16) >> 1;   // A & V(trans) pattern
    int rowK = ((lane & 16) >> 1) + (lane & 7), colK8 = (lane & 8); // K(B) pattern

    auto stageKV = [&](int kt, int buf) {
        int kj0 = kt * 64;
        uint32_t kb = bufBase + (uint32_t)buf * 36864u;
        for (int i = t; i < 512; i += 128) {
            int rr = i >> 3, c = i & 7;
            size_t src = (size_t)(b * TT + kj0 + rr) * 8 + c;
            uint32_t d = (uint32_t)(rr * 144 + c * 16);
            cp16(kb + d,          KH + src);
            cp16(kb + 9216 + d,   KL + src);
            cp16(kb + 18432 + d,  VH + src);
            cp16(kb + 27648 + d,  VL + src);
        }
    };

    // stage Q (normal stores) + kick off first KV tile
    for (int i = t; i < 512; i += 128) {
        int rr = i >> 3, c = i & 7;
        size_t src = (size_t)(b * TT + qi0 + rr) * 8 + c;
        *(uint4*)(dyn + rr * 144 + c * 16) = QH[src];
        *(uint4*)(dyn + 9216 + rr * 144 + c * 16) = QL[src];
    }
    stageKV(kt0, 0);
    CP_COMMIT();
    __syncthreads();

    uint32_t qh[4][4], ql[4][4];
#pragma unroll
    for (int j = 0; j < 4; j++) {
        uint32_t off = (uint32_t)((warp * 16 + rowA) * SROW + j * 16 + colA8) * 2;
        ldsm4(qh[j][0], qh[j][1], qh[j][2], qh[j][3], uQh + off);
        ldsm4(ql[j][0], ql[j][1], ql[j][2], ql[j][3], uQl + off);
    }

    float Oacc[8][4];
#pragma unroll
    for (int nt = 0; nt < 8; nt++)
#pragma unroll
        for (int e = 0; e < 4; e++) Oacc[nt][e] = 0.f;
    float lp0 = 0.f, lp1 = 0.f;

#pragma unroll 1
    for (int kt = kt0; kt < kt1; kt++) {
        int buf = (kt - kt0) & 1;
        if (kt + 1 < kt1) { stageKV(kt + 1, buf ^ 1); CP_COMMIT(); CP_WAIT1(); }
        else               CP_WAIT0();
        __syncthreads();

        uint32_t uK = bufBase + (uint32_t)buf * 36864u;
        uint32_t uKh = uK, uKl = uK + 9216, uVh = uK + 18432, uVl = uK + 27648;
        int kj0 = kt * 64;

        // S = Q K^T (split-bf16, 3 products)
        float S[8][4];
#pragma unroll
        for (int nt = 0; nt < 8; nt++)
#pragma unroll
            for (int e = 0; e < 4; e++) S[nt][e] = 0.f;
#pragma unroll
        for (int j = 0; j < 4; j++) {
#pragma unroll
            for (int np = 0; np < 4; np++) {
                uint32_t off = (uint32_t)((np * 16 + rowK) * SROW + j * 16 + colK8) * 2;
                uint32_t kh0, kh1, kh2, kh3, kl0, kl1, kl2, kl3;
                ldsm4(kh0, kh1, kh2, kh3, uKh + off);
                ldsm4(kl0, kl1, kl2, kl3, uKl + off);
                mma_bf16(S[2*np],   qh[j], kh0, kh1);
                mma_bf16(S[2*np],   qh[j], kl0, kl1);
                mma_bf16(S[2*np],   ql[j], kh0, kh1);
                mma_bf16(S[2*np+1], qh[j], kh2, kh3);
                mma_bf16(S[2*np+1], qh[j], kl2, kl3);
                mma_bf16(S[2*np+1], ql[j], kh2, kh3);
            }
        }

        // weights: masked -> exactly 1.0; kept -> exp(s/8)
#pragma unroll
        for (int nt = 0; nt < 8; nt++) {
            int col0 = kj0 + nt * 8 + 2 * tig;
            S[nt][0] = (!pad0 && col0     <= r0 + 1) ? __expf(S[nt][0] * 0.125f) : 1.0f;
            S[nt][1] = (!pad0 && col0 + 1 <= r0 + 1) ? __expf(S[nt][1] * 0.125f) : 1.0f;
            S[nt][2] = (!pad1 && col0     <= r1 + 1) ? __expf(S[nt][2] * 0.125f) : 1.0f;
            S[nt][3] = (!pad1 && col0 + 1 <= r1 + 1) ? __expf(S[nt][3] * 0.125f) : 1.0f;
            lp0 += S[nt][0] + S[nt][1];
            lp1 += S[nt][2] + S[nt][3];
        }

        // O += P V (P re-split to bf16 hi/lo A-fragments; V via ldmatrix.trans)
#pragma unroll
        for (int j = 0; j < 4; j++) {
            uint32_t ah[4], al[4];
            cvt_pair(make_float2(S[2*j][0],   S[2*j][1]),   ah[0], al[0]);
            cvt_pair(make_float2(S[2*j][2],   S[2*j][3]),   ah[1], al[1]);
            cvt_pair(make_float2(S[2*j+1][0], S[2*j+1][1]), ah[2], al[2]);
            cvt_pair(make_float2(S[2*j+1][2], S[2*j+1][3]), ah[3], al[3]);
#pragma unroll
            for (int np = 0; np < 4; np++) {
                uint32_t off = (uint32_t)((j * 16 + rowA) * SROW + np * 16 + colA8) * 2;
                uint32_t vh0, vh1, vh2, vh3, vl0, vl1, vl2, vl3;
                ldsm4t(vh0, vh1, vh2, vh3, uVh + off);
                ldsm4t(vl0, vl1, vl2, vl3, uVl + off);
                mma_bf16(Oacc[2*np],   ah, vh0, vh1);
                mma_bf16(Oacc[2*np],   ah, vl0, vl1);
                mma_bf16(Oacc[2*np],   al, vh0, vh1);
                mma_bf16(Oacc[2*np+1], ah, vh2, vh3);
                mma_bf16(Oacc[2*np+1], ah, vl2, vl3);
                mma_bf16(Oacc[2*np+1], al, vh2, vh3);
            }
        }
        __syncthreads();
    }

    lp0 += __shfl_xor_sync(0xffffffffu, lp0, 1, 4);
    lp0 += __shfl_xor_sync(0xffffffffu, lp0, 2, 4);
    lp1 += __shfl_xor_sync(0xffffffffu, lp1, 1, 4);
    lp1 += __shfl_xor_sync(0xffffffffu, lp1, 2, 4);

    // fully-masked suffix (weight exactly 1.0): V column sums + count
    if (last && kt_end < 32) {
        if (t < 64) {
            float a = 0.f;
            for (int kt2 = kt_end; kt2 < 32; kt2++) a += g_Vtile[b][kt2][t];
            sSuf[t] = a;
        }
        __syncthreads();
        float cnt = (float)(TT - kt_end * 64);
        lp0 += cnt; lp1 += cnt;
#pragma unroll
        for (int nt = 0; nt < 8; nt++) {
            int col = nt * 8 + 2 * tig;
            float s0 = sSuf[col], s1 = sSuf[col + 1];
            Oacc[nt][0] += s0; Oacc[nt][1] += s1;
            Oacc[nt][2] += s0; Oacc[nt][3] += s1;
        }
    }

    if (tig == 0) {
        g_accL[chunk][(size_t)b * TT + r0] = lp0;
        g_accL[chunk][(size_t)b * TT + r1] = lp1;
    }
#pragma unroll
    for (int nt = 0; nt < 8; nt++) {
        int col = nt * 8 + 2 * tig;
        *(float2*)&g_accO[chunk][((size_t)b * TT + r0) * HH + col] =
            make_float2(Oacc[nt][0], Oacc[nt][1]);
        *(float2*)&g_accO[chunk][((size_t)b * TT + r1) * HH + col] =
            make_float2(Oacc[nt][2], Oacc[nt][3]);
    }
}

// ---------------- combine partials, divide ----------------
__global__ void final_kernel(float* __restrict__ out)
{
    int idx = blockIdx.x * 256 + threadIdx.x;
    int row = idx >> 4;
    int qt = (row & (TT - 1)) >> 6;
    int kte = qt + 2; if (kte > 32) kte = 32;
    int ns = (kte + 3) >> 2;
    float l = 0.f;
    float4 o = make_float4(0.f, 0.f, 0.f, 0.f);
#pragma unroll 1
    for (int s = 0; s < ns; s++) {
        l += g_accL[s][row];
        float4 p = ((const float4*)g_accO[s])[idx];
        o.x += p.x; o.y += p.y; o.z += p.z; o.w += p.w;
    }
    float inv = 1.f / l;
    ((float4*)out)[idx] = make_float4(o.x*inv, o.y*inv, o.z*inv, o.w*inv);
}

extern "C" void kernel_launch(void* const* d_in, const int* in_sizes, int n_in,
                              void* d_out, int out_size)
{
    const float* q  = (const float*)d_in[0];
    const float* k  = (const float*)d_in[1];
    const float* v  = (const float*)d_in[2];
    const float* Wq = (const float*)d_in[3];
    const float* Wk = (const float*)d_in[4];
    const float* Wv = (const float*)d_in[5];
    const int* pad  = (const int*)d_in[6];
    float* out = (float*)d_out;

    const int attn_smem = 92160 + 256;   // Q(hi/lo) + 2x double-buffered KV(hi/lo) + suffix
    cudaFuncSetAttribute(attn_kernel, cudaFuncAttributeMaxDynamicSharedMemorySize, attn_smem);

    wprep_kernel<<<dim3(3, 128), 256>>>(Wq, Wk, Wv);
    proj_kernel<<<dim3(64, 3), 128>>>(q, k, v);
    attn_kernel<<<604, 128, attn_smem>>>(pad);
    final_kernel<<<BB * TT * HH / 4 / 256, 256>>>(out);
}

// round 11
// speedup vs baseline: 3.0137x; 1.1607x over previous
#include <cuda_runtime.h>
#include <cuda_bf16.h>
#include <cstdint>

#define BB 4
#define TT 2048
#define CC 1024
#define HH 64

__device__ uint32_t g_WpHi[3][HH][CC/2];
__device__ uint32_t g_WpLo[3][HH][CC/2];
__device__ uint32_t g_OHi[3][BB*TT*HH/2];          // projected Q/K/V, packed bf16x2 hi
__device__ uint32_t g_OLo[3][BB*TT*HH/2];          // lo
__device__ float g_Vtile[BB][32][HH];
__device__ float g_accO[8][BB*TT*HH];
__device__ float g_accL[8][BB*TT];

// pack float2 -> bf16x2 hi + bf16x2 lo (split-bf16); low 16 bits = .x
__device__ __forceinline__ void cvt_pair(float2 f, uint32_t& hi, uint32_t& lo) {
    __nv_bfloat162 h = __float22bfloat162_rn(f);
    hi = *reinterpret_cast<uint32_t*>(&h);
    float h0 = __uint_as_float(hi << 16);
    float h1 = __uint_as_float(hi & 0xffff0000u);
    __nv_bfloat162 l = __float22bfloat162_rn(make_float2(f.x - h0, f.y - h1));
    lo = *reinterpret_cast<uint32_t*>(&l);
}

__device__ __forceinline__ void mma_bf16(float* c, const uint32_t* a, uint32_t b0, uint32_t b1) {
    asm("mma.sync.aligned.m16n8k16.row.col.f32.bf16.bf16.f32 "
        "{%0,%1,%2,%3}, {%4,%5,%6,%7}, {%8,%9}, {%0,%1,%2,%3};"
        : "+f"(c[0]), "+f"(c[1]), "+f"(c[2]), "+f"(c[3])
        : "r"(a[0]), "r"(a[1]), "r"(a[2]), "r"(a[3]), "r"(b0), "r"(b1));
}
__device__ __forceinline__ void ldsm4(uint32_t& r0, uint32_t& r1, uint32_t& r2, uint32_t& r3, uint32_t a) {
    asm volatile("ldmatrix.sync.aligned.m8n8.x4.shared.b16 {%0,%1,%2,%3}, [%4];"
                 : "=r"(r0), "=r"(r1), "=r"(r2), "=r"(r3) : "r"(a));
}
__device__ __forceinline__ void ldsm4t(uint32_t& r0, uint32_t& r1, uint32_t& r2, uint32_t& r3, uint32_t a) {
    asm volatile("ldmatrix.sync.aligned.m8n8.x4.trans.shared.b16 {%0,%1,%2,%3}, [%4];"
                 : "=r"(r0), "=r"(r1), "=r"(r2), "=r"(r3) : "r"(a));
}
__device__ __forceinline__ uint32_t smem_u32(const void* p) {
    uint32_t a;
    asm("{ .reg .u64 t; cvta.to.shared.u64 t, %1; cvt.u32.u64 %0, t; }" : "=r"(a) : "l"(p));
    return a;
}
__device__ __forceinline__ void cp16(uint32_t dst, const void* src) {
    asm volatile("cp.async.cg.shared.global [%0], [%1], 16;" :: "r"(dst), "l"(src));
}
#define CP_COMMIT() asm volatile("cp.async.commit_group;" ::: "memory")
#define CP_WAIT1()  asm volatile("cp.async.wait_group 1;" ::: "memory")
#define CP_WAIT0()  asm volatile("cp.async.wait_group 0;" ::: "memory")

// ---------------- W prepack ----------------
__global__ void wprep_kernel(const float* __restrict__ Wq, const float* __restrict__ Wk,
                             const float* __restrict__ Wv)
{
    int z = blockIdx.x;
    const float* W = (z == 0) ? Wq : (z == 1) ? Wk : Wv;
    int idx = blockIdx.y * 256 + threadIdx.x;
    int col = idx & 63, j = idx >> 6;
    uint32_t hi, lo;
    cvt_pair(make_float2(W[(size_t)(2*j) * HH + col], W[(size_t)(2*j+1) * HH + col]), hi, lo);
    g_WpHi[z][col][j] = hi;
    g_WpLo[z][col][j] = lo;
}

// ---------------- Projection: mma.sync bf16x3; 64-row tiles; epilogue emits hi/lo + V sums ------
__global__ __launch_bounds__(128) void proj_kernel(
    const float* __restrict__ q, const float* __restrict__ k, const float* __restrict__ v)
{
    int z = blockIdx.y;
    const float* X = (z == 0) ? q : (z == 1) ? k : v;
    const uint32_t* WH = &g_WpHi[z][0][0];
    const uint32_t* WL = &g_WpLo[z][0][0];

    __shared__ uint32_t sBh[64][68];
    __shared__ uint32_t sBl[64][68];
    __shared__ float sVs[4][64];

    int t = threadIdx.x, warp = t >> 5, lane = t & 31;
    int g = lane >> 2, tig = lane & 3;
    int rowC = blockIdx.x * 64;
    int row0 = rowC + warp * 16;

    const float* pA0 = X + (size_t)(row0 + g)     * CC + 2 * tig;
    const float* pA1 = X + (size_t)(row0 + g + 8) * CC + 2 * tig;

    float acc[8][4];
#pragma unroll
    for (int j = 0; j < 8; j++)
#pragma unroll
        for (int e = 0; e < 4; e++) acc[j][e] = 0.f;

    for (int c = 0; c < 8; c++) {
        for (int i = t; i < 1024; i += 128) {
            int col = i >> 4, f4 = (i & 15) << 2;
            *(uint4*)&sBh[col][f4] = *(const uint4*)&WH[col * (CC/2) + c * 64 + f4];
            *(uint4*)&sBl[col][f4] = *(const uint4*)&WL[col * (CC/2) + c * 64 + f4];
        }
        __syncthreads();
#pragma unroll
        for (int s = 0; s < 8; s++) {
            int k0 = c * 128 + s * 16;
            uint32_t ah[4], al[4];
            cvt_pair(*(const float2*)(pA0 + k0),     ah[0], al[0]);
            cvt_pair(*(const float2*)(pA1 + k0),     ah[1], al[1]);
            cvt_pair(*(const float2*)(pA0 + k0 + 8), ah[2], al[2]);
            cvt_pair(*(const float2*)(pA1 + k0 + 8), ah[3], al[3]);
#pragma unroll
            for (int j = 0; j < 8; j++) {
                int colr = j * 8 + g;
                uint32_t bh0 = sBh[colr][s*8 + tig], bh1 = sBh[colr][s*8 + tig + 4];
                uint32_t bl0 = sBl[colr][s*8 + tig], bl1 = sBl[colr][s*8 + tig + 4];
                mma_bf16(acc[j], ah, bh0, bh1);
                mma_bf16(acc[j], ah, bl0, bl1);
                mma_bf16(acc[j], al, bh0, bh1);
            }
        }
        __syncthreads();
    }

    uint32_t* OH = g_OHi[z];
    uint32_t* OL = g_OLo[z];
    int r0 = row0 + g;
#pragma unroll
    for (int j = 0; j < 8; j++) {
        int col = j * 8 + 2 * tig;
        uint32_t hi, lo;
        cvt_pair(make_float2(acc[j][0], acc[j][1]), hi, lo);
        OH[((size_t)r0 * HH + col) >> 1] = hi;
        OL[((size_t)r0 * HH + col) >> 1] = lo;
        cvt_pair(make_float2(acc[j][2], acc[j][3]), hi, lo);
        OH[((size_t)(r0 + 8) * HH + col) >> 1] = hi;
        OL[((size_t)(r0 + 8) * HH + col) >> 1] = lo;
    }

    // V tile column sums (this CTA owns exactly one 64-row tile)
    if (z == 2) {
        float cs0[8], cs1[8];
#pragma unroll
        for (int j = 0; j < 8; j++) {
            cs0[j] = acc[j][0] + acc[j][2];
            cs1[j] = acc[j][1] + acc[j][3];
        }
#pragma unroll
        for (int off = 4; off < 32; off <<= 1)
#pragma unroll
            for (int j = 0; j < 8; j++) {
                cs0[j] += __shfl_xor_sync(0xffffffffu, cs0[j], off);
                cs1[j] += __shfl_xor_sync(0xffffffffu, cs1[j], off);
            }
        if (lane < 4) {
#pragma unroll
            for (int j = 0; j < 8; j++) {
                sVs[warp][j * 8 + 2 * lane] = cs0[j];
                sVs[warp][j * 8 + 2 * lane + 1] = cs1[j];
            }
        }
        __syncthreads();
        if (t < 64) {
            int b2 = rowC >> 11, tb = (rowC & 2047) >> 6;
            g_Vtile[b2][tb][t] = sVs[0][t] + sVs[1][t] + sVs[2][t] + sVs[3][t];
        }
    }
}

// ---------------- Attention: tensor-core flash, split-KV (4 tiles), cp.async pipeline -----------
#define SROW 72   // smem tile row stride in bf16 (144 B)
__global__ __launch_bounds__(128) void attn_kernel(const int* __restrict__ pad)
{
    extern __shared__ char dyn[];
    uint32_t base = smem_u32(dyn);
    // double-buffered KV only: buf*36864 + {Kh:0, Kl:9216, Vh:18432, Vl:27648}
    float* sSuf = (float*)(dyn + 73728);

    int u = blockIdx.x;
    int b = u & 3, w = u >> 2;
    int qt = 0, chunk = 0, rem = w;
#pragma unroll 1
    for (int q2 = 31; q2 >= 0; q2--) {
        int kte = q2 + 2; if (kte > 32) kte = 32;
        int s = (kte + 3) >> 2;
        if (rem < s) { qt = q2; chunk = rem; break; }
        rem -= s;
    }
    int kt_end = qt + 2; if (kt_end > 32) kt_end = 32;
    int kt0 = chunk * 4, kt1 = kt0 + 4; if (kt1 > kt_end) kt1 = kt_end;
    bool last = (kt1 == kt_end);
    int qi0 = qt * 64;

    const uint32_t* QH0 = g_OHi[0];
    const uint32_t* QL0 = g_OLo[0];
    const uint4* KH = (const uint4*)g_OHi[1];
    const uint4* KL = (const uint4*)g_OLo[1];
    const uint4* VH = (const uint4*)g_OHi[2];
    const uint4* VL = (const uint4*)g_OLo[2];

    int t = threadIdx.x, warp = t >> 5, lane = t & 31;
    int g = lane >> 2, tig = lane & 3;
    int r0 = qi0 + warp * 16 + g, r1 = r0 + 8;
    bool pad0 = (pad[b * TT + r0] == 1);
    bool pad1 = (pad[b * TT + r1] == 1);

    int rowA = (lane & 8) + (lane & 7), colA8 = (lane & 16) >> 1;   // V(trans) pattern
    int rowK = ((lane & 16) >> 1) + (lane & 7), colK8 = (lane & 8); // K(B) pattern

    auto stageKV = [&](int kt, int buf) {
        int kj0 = kt * 64;
        uint32_t kb = base + (uint32_t)buf * 36864u;
        for (int i = t; i < 512; i += 128) {
            int rr = i >> 3, c = i & 7;
            size_t src = (size_t)(b * TT + kj0 + rr) * 8 + c;
            uint32_t d = (uint32_t)(rr * 144 + c * 16);
            cp16(kb + d,          KH + src);
            cp16(kb + 9216 + d,   KL + src);
            cp16(kb + 18432 + d,  VH + src);
            cp16(kb + 27648 + d,  VL + src);
        }
    };

    stageKV(kt0, 0);
    CP_COMMIT();

    // Q fragments straight from global (A-frag: a0=(g,2c) a1=(g+8,2c) a2=(g,2c+8) a3=(g+8,2c+8))
    uint32_t qh[4][4], ql[4][4];
    {
        size_t b0 = ((size_t)(b * TT) + r0) * 32 + tig;
        size_t b1 = ((size_t)(b * TT) + r1) * 32 + tig;
#pragma unroll
        for (int j = 0; j < 4; j++) {
            qh[j][0] = QH0[b0 + j*8];     qh[j][1] = QH0[b1 + j*8];
            qh[j][2] = QH0[b0 + j*8 + 4]; qh[j][3] = QH0[b1 + j*8 + 4];
            ql[j][0] = QL0[b0 + j*8];     ql[j][1] = QL0[b1 + j*8];
            ql[j][2] = QL0[b0 + j*8 + 4]; ql[j][3] = QL0[b1 + j*8 + 4];
        }
    }

    float Oacc[8][4];
#pragma unroll
    for (int nt = 0; nt < 8; nt++)
#pragma unroll
        for (int e = 0; e < 4; e++) Oacc[nt][e] = 0.f;
    float lp0 = 0.f, lp1 = 0.f;

#pragma unroll 1
    for (int kt = kt0; kt < kt1; kt++) {
        int buf = (kt - kt0) & 1;
        if (kt + 1 < kt1) { stageKV(kt + 1, buf ^ 1); CP_COMMIT(); CP_WAIT1(); }
        else               CP_WAIT0();
        __syncthreads();

        uint32_t uK = base + (uint32_t)buf * 36864u;
        uint32_t uKh = uK, uKl = uK + 9216, uVh = uK + 18432, uVl = uK + 27648;
        int kj0 = kt * 64;

        // S = Q K^T (split-bf16, 3 products)
        float S[8][4];
#pragma unroll
        for (int nt = 0; nt < 8; nt++)
#pragma unroll
            for (int e = 0; e < 4; e++) S[nt][e] = 0.f;
#pragma unroll
        for (int j = 0; j < 4; j++) {
#pragma unroll
            for (int np = 0; np < 4; np++) {
                uint32_t off = (uint32_t)((np * 16 + rowK) * SROW + j * 16 + colK8) * 2;
                uint32_t kh0, kh1, kh2, kh3, kl0, kl1, kl2, kl3;
                ldsm4(kh0, kh1, kh2, kh3, uKh + off);
                ldsm4(kl0, kl1, kl2, kl3, uKl + off);
                mma_bf16(S[2*np],   qh[j], kh0, kh1);
                mma_bf16(S[2*np],   qh[j], kl0, kl1);
                mma_bf16(S[2*np],   ql[j], kh0, kh1);
                mma_bf16(S[2*np+1], qh[j], kh2, kh3);
                mma_bf16(S[2*np+1], qh[j], kl2, kl3);
                mma_bf16(S[2*np+1], ql[j], kh2, kh3);
            }
        }

        // weights: masked -> exactly 1.0; kept -> exp(s/8)
#pragma unroll
        for (int nt = 0; nt < 8; nt++) {
            int col0 = kj0 + nt * 8 + 2 * tig;
            S[nt][0] = (!pad0 && col0     <= r0 + 1) ? __expf(S[nt][0] * 0.125f) : 1.0f;
            S[nt][1] = (!pad0 && col0 + 1 <= r0 + 1) ? __expf(S[nt][1] * 0.125f) : 1.0f;
            S[nt][2] = (!pad1 && col0     <= r1 + 1) ? __expf(S[nt][2] * 0.125f) : 1.0f;
            S[nt][3] = (!pad1 && col0 + 1 <= r1 + 1) ? __expf(S[nt][3] * 0.125f) : 1.0f;
            lp0 += S[nt][0] + S[nt][1];
            lp1 += S[nt][2] + S[nt][3];
        }

        // O += P V (P re-split to bf16 hi/lo A-fragments; V via ldmatrix.trans)
#pragma unroll
        for (int j = 0; j < 4; j++) {
            uint32_t ah[4], al[4];
            cvt_pair(make_float2(S[2*j][0],   S[2*j][1]),   ah[0], al[0]);
            cvt_pair(make_float2(S[2*j][2],   S[2*j][3]),   ah[1], al[1]);
            cvt_pair(make_float2(S[2*j+1][0], S[2*j+1][1]), ah[2], al[2]);
            cvt_pair(make_float2(S[2*j+1][2], S[2*j+1][3]), ah[3], al[3]);
#pragma unroll
            for (int np = 0; np < 4; np++) {
                uint32_t off = (uint32_t)((j * 16 + rowA) * SROW + np * 16 + colA8) * 2;
                uint32_t vh0, vh1, vh2, vh3, vl0, vl1, vl2, vl3;
                ldsm4t(vh0, vh1, vh2, vh3, uVh + off);
                ldsm4t(vl0, vl1, vl2, vl3, uVl + off);
                mma_bf16(Oacc[2*np],   ah, vh0, vh1);
                mma_bf16(Oacc[2*np],   ah, vl0, vl1);
                mma_bf16(Oacc[2*np],   al, vh0, vh1);
                mma_bf16(Oacc[2*np+1], ah, vh2, vh3);
                mma_bf16(Oacc[2*np+1], ah, vl2, vl3);
                mma_bf16(Oacc[2*np+1], al, vh2, vh3);
            }
        }
        __syncthreads();
    }

    lp0 += __shfl_xor_sync(0xffffffffu, lp0, 1, 4);
    lp0 += __shfl_xor_sync(0xffffffffu, lp0, 2, 4);
    lp1 += __shfl_xor_sync(0xffffffffu, lp1, 1, 4);
    lp1 += __shfl_xor_sync(0xffffffffu, lp1, 2, 4);

    // fully-masked suffix (weight exactly 1.0): V column sums + count
    if (last && kt_end < 32) {
        if (t < 64) {
            float a = 0.f;
            for (int kt2 = kt_end; kt2 < 32; kt2++) a += g_Vtile[b][kt2][t];
            sSuf[t] = a;
        }
        __syncthreads();
        float cnt = (float)(TT - kt_end * 64);
        lp0 += cnt; lp1 += cnt;
#pragma unroll
        for (int nt = 0; nt < 8; nt++) {
            int col = nt * 8 + 2 * tig;
            float s0 = sSuf[col], s1 = sSuf[col + 1];
            Oacc[nt][0] += s0; Oacc[nt][1] += s1;
            Oacc[nt][2] += s0; Oacc[nt][3] += s1;
        }
    }

    if (tig == 0) {
        g_accL[chunk][(size_t)b * TT + r0] = lp0;
        g_accL[chunk][(size_t)b * TT + r1] = lp1;
    }
#pragma unroll
    for (int nt = 0; nt < 8; nt++) {
        int col = nt * 8 + 2 * tig;
        *(float2*)&g_accO[chunk][((size_t)b * TT + r0) * HH + col] =
            make_float2(Oacc[nt][0], Oacc[nt][1]);
        *(float2*)&g_accO[chunk][((size_t)b * TT + r1) * HH + col] =
            make_float2(Oacc[nt][2], Oacc[nt][3]);
    }
}

// ---------------- combine partials, divide (unrolled predicated -> MLP) ----------------
__global__ void final_kernel(float* __restrict__ out)
{
    int idx = blockIdx.x * 256 + threadIdx.x;
    int row = idx >> 4;
    int qt = (row & (TT - 1)) >> 6;
    int kte = qt + 2; if (kte > 32) kte = 32;
    int ns = (kte + 3) >> 2;
    float l = 0.f;
    float4 o = make_float4(0.f, 0.f, 0.f, 0.f);
#pragma unroll
    for (int s = 0; s < 8; s++) {
        if (s < ns) {
            l += g_accL[s][row];
            float4 p = ((const float4*)g_accO[s])[idx];
            o.x += p.x; o.y += p.y; o.z += p.z; o.w += p.w;
        }
    }
    float inv = 1.f / l;
    ((float4*)out)[idx] = make_float4(o.x*inv, o.y*inv, o.z*inv, o.w*inv);
}

extern "C" void kernel_launch(void* const* d_in, const int* in_sizes, int n_in,
                              void* d_out, int out_size)
{
    const float* q  = (const float*)d_in[0];
    const float* k  = (const float*)d_in[1];
    const float* v  = (const float*)d_in[2];
    const float* Wq = (const float*)d_in[3];
    const float* Wk = (const float*)d_in[4];
    const float* Wv = (const float*)d_in[5];
    const int* pad  = (const int*)d_in[6];
    float* out = (float*)d_out;

    const int attn_smem = 73728 + 256;   // 2x double-buffered KV(hi/lo) + suffix
    cudaFuncSetAttribute(attn_kernel, cudaFuncAttributeMaxDynamicSharedMemorySize, attn_smem);

    wprep_kernel<<<dim3(3, 128), 256>>>(Wq, Wk, Wv);
    proj_kernel<<<dim3(128, 3), 128>>>(q, k, v);
    attn_kernel<<<604, 128, attn_smem>>>(pad);
    final_kernel<<<BB * TT * HH / 4 / 256, 256>>>(out);
}

// round 13
// speedup vs baseline: 3.3423x; 1.1090x over previous
#include <cuda_runtime.h>
#include <cuda_bf16.h>
#include <cuda_fp16.h>
#include <cstdint>

#define BB 4
#define TT 2048
#define CC 1024
#define HH 64

__device__ uint32_t g_WpHi[3][HH][CC/2];
__device__ uint32_t g_WpLo[3][HH][CC/2];
__device__ uint32_t g_OHi[3][BB*TT*HH/2];          // projected Q/K/V, packed fp16x2 hi
__device__ uint32_t g_OLo[3][BB*TT*HH/2];          // lo (only Q's is consumed)
__device__ float g_Vtile[BB][32][HH];
__device__ float g_accO[8][BB*TT*HH];
__device__ float g_accL[8][BB*TT];

// pack float2 -> bf16x2 hi + bf16x2 lo (split-bf16); used by proj internals
__device__ __forceinline__ void cvt_pair(float2 f, uint32_t& hi, uint32_t& lo) {
    __nv_bfloat162 h = __float22bfloat162_rn(f);
    hi = *reinterpret_cast<uint32_t*>(&h);
    float h0 = __uint_as_float(hi << 16);
    float h1 = __uint_as_float(hi & 0xffff0000u);
    __nv_bfloat162 l = __float22bfloat162_rn(make_float2(f.x - h0, f.y - h1));
    lo = *reinterpret_cast<uint32_t*>(&l);
}
// pack float2 -> fp16x2 hi + fp16x2 lo (split-fp16); attention operands
__device__ __forceinline__ void cvt_pairh(float2 f, uint32_t& hi, uint32_t& lo) {
    __half2 h = __float22half2_rn(f);
    hi = *reinterpret_cast<uint32_t*>(&h);
    float2 hf = __half22float2(h);
    __half2 l = __float22half2_rn(make_float2(f.x - hf.x, f.y - hf.y));
    lo = *reinterpret_cast<uint32_t*>(&l);
}

__device__ __forceinline__ void mma_bf16(float* c, const uint32_t* a, uint32_t b0, uint32_t b1) {
    asm("mma.sync.aligned.m16n8k16.row.col.f32.bf16.bf16.f32 "
        "{%0,%1,%2,%3}, {%4,%5,%6,%7}, {%8,%9}, {%0,%1,%2,%3};"
        : "+f"(c[0]), "+f"(c[1]), "+f"(c[2]), "+f"(c[3])
        : "r"(a[0]), "r"(a[1]), "r"(a[2]), "r"(a[3]), "r"(b0), "r"(b1));
}
__device__ __forceinline__ void mma_f16(float* c, const uint32_t* a, uint32_t b0, uint32_t b1) {
    asm("mma.sync.aligned.m16n8k16.row.col.f32.f16.f16.f32 "
        "{%0,%1,%2,%3}, {%4,%5,%6,%7}, {%8,%9}, {%0,%1,%2,%3};"
        : "+f"(c[0]), "+f"(c[1]), "+f"(c[2]), "+f"(c[3])
        : "r"(a[0]), "r"(a[1]), "r"(a[2]), "r"(a[3]), "r"(b0), "r"(b1));
}
__device__ __forceinline__ void ldsm4(uint32_t& r0, uint32_t& r1, uint32_t& r2, uint32_t& r3, uint32_t a) {
    asm volatile("ldmatrix.sync.aligned.m8n8.x4.shared.b16 {%0,%1,%2,%3}, [%4];"
                 : "=r"(r0), "=r"(r1), "=r"(r2), "=r"(r3) : "r"(a));
}
__device__ __forceinline__ void ldsm4t(uint32_t& r0, uint32_t& r1, uint32_t& r2, uint32_t& r3, uint32_t a) {
    asm volatile("ldmatrix.sync.aligned.m8n8.x4.trans.shared.b16 {%0,%1,%2,%3}, [%4];"
                 : "=r"(r0), "=r"(r1), "=r"(r2), "=r"(r3) : "r"(a));
}
__device__ __forceinline__ uint32_t smem_u32(const void* p) {
    uint32_t a;
    asm("{ .reg .u64 t; cvta.to.shared.u64 t, %1; cvt.u32.u64 %0, t; }" : "=r"(a) : "l"(p));
    return a;
}
__device__ __forceinline__ void cp16(uint32_t dst, const void* src) {
    asm volatile("cp.async.cg.shared.global [%0], [%1], 16;" :: "r"(dst), "l"(src));
}
#define CP_COMMIT() asm volatile("cp.async.commit_group;" ::: "memory")
#define CP_WAIT1()  asm volatile("cp.async.wait_group 1;" ::: "memory")
#define CP_WAIT0()  asm volatile("cp.async.wait_group 0;" ::: "memory")

// ---------------- W prepack (bf16 split for proj) ----------------
__global__ void wprep_kernel(const float* __restrict__ Wq, const float* __restrict__ Wk,
                             const float* __restrict__ Wv)
{
    int z = blockIdx.x;
    const float* W = (z == 0) ? Wq : (z == 1) ? Wk : Wv;
    int idx = blockIdx.y * 256 + threadIdx.x;
    int col = idx & 63, j = idx >> 6;
    uint32_t hi, lo;
    cvt_pair(make_float2(W[(size_t)(2*j) * HH + col], W[(size_t)(2*j+1) * HH + col]), hi, lo);
    g_WpHi[z][col][j] = hi;
    g_WpLo[z][col][j] = lo;
}

// ---------------- Projection: mma.sync bf16x3; epilogue emits fp16 hi/lo + V sums ------
__global__ __launch_bounds__(128) void proj_kernel(
    const float* __restrict__ q, const float* __restrict__ k, const float* __restrict__ v)
{
    int z = blockIdx.y;
    const float* X = (z == 0) ? q : (z == 1) ? k : v;
    const uint32_t* WH = &g_WpHi[z][0][0];
    const uint32_t* WL = &g_WpLo[z][0][0];

    __shared__ uint32_t sBh[64][68];
    __shared__ uint32_t sBl[64][68];
    __shared__ float sVs[4][64];

    int t = threadIdx.x, warp = t >> 5, lane = t & 31;
    int g = lane >> 2, tig = lane & 3;
    int rowC = blockIdx.x * 64;
    int row0 = rowC + warp * 16;

    const float* pA0 = X + (size_t)(row0 + g)     * CC + 2 * tig;
    const float* pA1 = X + (size_t)(row0 + g + 8) * CC + 2 * tig;

    float acc[8][4];
#pragma unroll
    for (int j = 0; j < 8; j++)
#pragma unroll
        for (int e = 0; e < 4; e++) acc[j][e] = 0.f;

    for (int c = 0; c < 8; c++) {
        for (int i = t; i < 1024; i += 128) {
            int col = i >> 4, f4 = (i & 15) << 2;
            *(uint4*)&sBh[col][f4] = *(const uint4*)&WH[col * (CC/2) + c * 64 + f4];
            *(uint4*)&sBl[col][f4] = *(const uint4*)&WL[col * (CC/2) + c * 64 + f4];
        }
        __syncthreads();
#pragma unroll
        for (int s = 0; s < 8; s++) {
            int k0 = c * 128 + s * 16;
            uint32_t ah[4], al[4];
            cvt_pair(*(const float2*)(pA0 + k0),     ah[0], al[0]);
            cvt_pair(*(const float2*)(pA1 + k0),     ah[1], al[1]);
            cvt_pair(*(const float2*)(pA0 + k0 + 8), ah[2], al[2]);
            cvt_pair(*(const float2*)(pA1 + k0 + 8), ah[3], al[3]);
#pragma unroll
            for (int j = 0; j < 8; j++) {
                int colr = j * 8 + g;
                uint32_t bh0 = sBh[colr][s*8 + tig], bh1 = sBh[colr][s*8 + tig + 4];
                uint32_t bl0 = sBl[colr][s*8 + tig], bl1 = sBl[colr][s*8 + tig + 4];
                mma_bf16(acc[j], ah, bh0, bh1);
                mma_bf16(acc[j], ah, bl0, bl1);
                mma_bf16(acc[j], al, bh0, bh1);
            }
        }
        __syncthreads();
    }

    uint32_t* OH = g_OHi[z];
    uint32_t* OL = g_OLo[z];
    int r0 = row0 + g;
#pragma unroll
    for (int j = 0; j < 8; j++) {
        int col = j * 8 + 2 * tig;
        uint32_t hi, lo;
        cvt_pairh(make_float2(acc[j][0], acc[j][1]), hi, lo);
        OH[((size_t)r0 * HH + col) >> 1] = hi;
        if (z == 0) OL[((size_t)r0 * HH + col) >> 1] = lo;
        cvt_pairh(make_float2(acc[j][2], acc[j][3]), hi, lo);
        OH[((size_t)(r0 + 8) * HH + col) >> 1] = hi;
        if (z == 0) OL[((size_t)(r0 + 8) * HH + col) >> 1] = lo;
    }

    // V tile column sums in fp32 (this CTA owns exactly one 64-row tile)
    if (z == 2) {
        float cs0[8], cs1[8];
#pragma unroll
        for (int j = 0; j < 8; j++) {
            cs0[j] = acc[j][0] + acc[j][2];
            cs1[j] = acc[j][1] + acc[j][3];
        }
#pragma unroll
        for (int off = 4; off < 32; off <<= 1)
#pragma unroll
            for (int j = 0; j < 8; j++) {
                cs0[j] += __shfl_xor_sync(0xffffffffu, cs0[j], off);
                cs1[j] += __shfl_xor_sync(0xffffffffu, cs1[j], off);
            }
        if (lane < 4) {
#pragma unroll
            for (int j = 0; j < 8; j++) {
                sVs[warp][j * 8 + 2 * lane] = cs0[j];
                sVs[warp][j * 8 + 2 * lane + 1] = cs1[j];
            }
        }
        __syncthreads();
        if (t < 64) {
            int b2 = rowC >> 11, tb = (rowC & 2047) >> 6;
            g_Vtile[b2][tb][t] = sVs[0][t] + sVs[1][t] + sVs[2][t] + sVs[3][t];
        }
    }
}

// ---------------- Attention: fp16 tensor-core flash; K/V single, Q/P split ---------------
#define SROW 72   // smem tile row stride in fp16 (144 B)
__global__ __launch_bounds__(128, 4) void attn_kernel(const int* __restrict__ pad)
{
    extern __shared__ char dyn[];
    uint32_t base = smem_u32(dyn);
    // double-buffered: buf*18432 + {K:0, V:9216}
    float* sSuf = (float*)(dyn + 36864);

    int u = blockIdx.x;
    int b = u & 3, w = u >> 2;
    int qt = 0, chunk = 0, rem = w;
#pragma unroll 1
    for (int q2 = 31; q2 >= 0; q2--) {
        int kte = q2 + 2; if (kte > 32) kte = 32;
        int s = (kte + 3) >> 2;
        if (rem < s) { qt = q2; chunk = rem; break; }
        rem -= s;
    }
    int kt_end = qt + 2; if (kt_end > 32) kt_end = 32;
    int kt0 = chunk * 4, kt1 = kt0 + 4; if (kt1 > kt_end) kt1 = kt_end;
    bool last = (kt1 == kt_end);
    int qi0 = qt * 64;

    const uint32_t* QH0 = g_OHi[0];
    const uint32_t* QL0 = g_OLo[0];
    const uint4* KH = (const uint4*)g_OHi[1];
    const uint4* VH = (const uint4*)g_OHi[2];

    int t = threadIdx.x, warp = t >> 5, lane = t & 31;
    int g = lane >> 2, tig = lane & 3;
    int r0 = qi0 + warp * 16 + g, r1 = r0 + 8;
    bool pad0 = (pad[b * TT + r0] == 1);
    bool pad1 = (pad[b * TT + r1] == 1);

    int rowA = (lane & 8) + (lane & 7), colA8 = (lane & 16) >> 1;   // V(trans) pattern
    int rowK = ((lane & 16) >> 1) + (lane & 7), colK8 = (lane & 8); // K(B) pattern

    auto stageKV = [&](int kt, int buf) {
        int kj0 = kt * 64;
        uint32_t kb = base + (uint32_t)buf * 18432u;
        for (int i = t; i < 512; i += 128) {
            int rr = i >> 3, c = i & 7;
            size_t src = (size_t)(b * TT + kj0 + rr) * 8 + c;
            uint32_t d = (uint32_t)(rr * 144 + c * 16);
            cp16(kb + d,        KH + src);
            cp16(kb + 9216 + d, VH + src);
        }
    };

    stageKV(kt0, 0);
    CP_COMMIT();

    // Q fragments straight from global (A-frag: a0=(g,2c) a1=(g+8,2c) a2=(g,2c+8) a3=(g+8,2c+8))
    uint32_t qh[4][4], ql[4][4];
    {
        size_t b0 = ((size_t)(b * TT) + r0) * 32 + tig;
        size_t b1 = ((size_t)(b * TT) + r1) * 32 + tig;
#pragma unroll
        for (int j = 0; j < 4; j++) {
            qh[j][0] = QH0[b0 + j*8];     qh[j][1] = QH0[b1 + j*8];
            qh[j][2] = QH0[b0 + j*8 + 4]; qh[j][3] = QH0[b1 + j*8 + 4];
            ql[j][0] = QL0[b0 + j*8];     ql[j][1] = QL0[b1 + j*8];
            ql[j][2] = QL0[b0 + j*8 + 4]; ql[j][3] = QL0[b1 + j*8 + 4];
        }
    }

    float Oacc[8][4];
#pragma unroll
    for (int nt = 0; nt < 8; nt++)
#pragma unroll
        for (int e = 0; e < 4; e++) Oacc[nt][e] = 0.f;
    float lp0 = 0.f, lp1 = 0.f;

#pragma unroll 1
    for (int kt = kt0; kt < kt1; kt++) {
        int buf = (kt - kt0) & 1;
        if (kt + 1 < kt1) { stageKV(kt + 1, buf ^ 1); CP_COMMIT(); CP_WAIT1(); }
        else               CP_WAIT0();
        __syncthreads();

        uint32_t uKh = base + (uint32_t)buf * 18432u;
        uint32_t uVh = uKh + 9216;
        int kj0 = kt * 64;

        // S = Qhi K + Qlo K   (K single-fp16)
        float S[8][4];
#pragma unroll
        for (int nt = 0; nt < 8; nt++)
#pragma unroll
            for (int e = 0; e < 4; e++) S[nt][e] = 0.f;
#pragma unroll
        for (int j = 0; j < 4; j++) {
#pragma unroll
            for (int np = 0; np < 4; np++) {
                uint32_t off = (uint32_t)((np * 16 + rowK) * SROW + j * 16 + colK8) * 2;
                uint32_t kh0, kh1, kh2, kh3;
                ldsm4(kh0, kh1, kh2, kh3, uKh + off);
                mma_f16(S[2*np],   qh[j], kh0, kh1);
                mma_f16(S[2*np],   ql[j], kh0, kh1);
                mma_f16(S[2*np+1], qh[j], kh2, kh3);
                mma_f16(S[2*np+1], ql[j], kh2, kh3);
            }
        }

        // weights: masked -> exactly 1.0; kept -> exp(s/8)
#pragma unroll
        for (int nt = 0; nt < 8; nt++) {
            int col0 = kj0 + nt * 8 + 2 * tig;
            S[nt][0] = (!pad0 && col0     <= r0 + 1) ? __expf(S[nt][0] * 0.125f) : 1.0f;
            S[nt][1] = (!pad0 && col0 + 1 <= r0 + 1) ? __expf(S[nt][1] * 0.125f) : 1.0f;
            S[nt][2] = (!pad1 && col0     <= r1 + 1) ? __expf(S[nt][2] * 0.125f) : 1.0f;
            S[nt][3] = (!pad1 && col0 + 1 <= r1 + 1) ? __expf(S[nt][3] * 0.125f) : 1.0f;
            lp0 += S[nt][0] + S[nt][1];
            lp1 += S[nt][2] + S[nt][3];
        }

        // O += P V (P split fp16 hi/lo; V single-fp16 via ldmatrix.trans)
#pragma unroll
        for (int j = 0; j < 4; j++) {
            uint32_t ah[4], al[4];
            cvt_pairh(make_float2(S[2*j][0],   S[2*j][1]),   ah[0], al[0]);
            cvt_pairh(make_float2(S[2*j][2],   S[2*j][3]),   ah[1], al[1]);
            cvt_pairh(make_float2(S[2*j+1][0], S[2*j+1][1]), ah[2], al[2]);
            cvt_pairh(make_float2(S[2*j+1][2], S[2*j+1][3]), ah[3], al[3]);
#pragma unroll
            for (int np = 0; np < 4; np++) {
                uint32_t off = (uint32_t)((j * 16 + rowA) * SROW + np * 16 + colA8) * 2;
                uint32_t vh0, vh1, vh2, vh3;
                ldsm4t(vh0, vh1, vh2, vh3, uVh + off);
                mma_f16(Oacc[2*np],   ah, vh0, vh1);
                mma_f16(Oacc[2*np],   al, vh0, vh1);
                mma_f16(Oacc[2*np+1], ah, vh2, vh3);
                mma_f16(Oacc[2*np+1], al, vh2, vh3);
            }
        }
        __syncthreads();
    }

    lp0 += __shfl_xor_sync(0xffffffffu, lp0, 1, 4);
    lp0 += __shfl_xor_sync(0xffffffffu, lp0, 2, 4);
    lp1 += __shfl_xor_sync(0xffffffffu, lp1, 1, 4);
    lp1 += __shfl_xor_sync(0xffffffffu, lp1, 2, 4);

    // fully-masked suffix (weight exactly 1.0): fp32 V column sums + count
    if (last && kt_end < 32) {
        if (t < 64) {
            float a = 0.f;
            for (int kt2 = kt_end; kt2 < 32; kt2++) a += g_Vtile[b][kt2][t];
            sSuf[t] = a;
        }
        __syncthreads();
        float cnt = (float)(TT - kt_end * 64);
        lp0 += cnt; lp1 += cnt;
#pragma unroll
        for (int nt = 0; nt < 8; nt++) {
            int col = nt * 8 + 2 * tig;
            float s0 = sSuf[col], s1 = sSuf[col + 1];
            Oacc[nt][0] += s0; Oacc[nt][1] += s1;
            Oacc[nt][2] += s0; Oacc[nt][3] += s1;
        }
    }

    if (tig == 0) {
        g_accL[chunk][(size_t)b * TT + r0] = lp0;
        g_accL[chunk][(size_t)b * TT + r1] = lp1;
    }
#pragma unroll
    for (int nt = 0; nt < 8; nt++) {
        int col = nt * 8 + 2 * tig;
        *(float2*)&g_accO[chunk][((size_t)b * TT + r0) * HH + col] =
            make_float2(Oacc[nt][0], Oacc[nt][1]);
        *(float2*)&g_accO[chunk][((size_t)b * TT + r1) * HH + col] =
            make_float2(Oacc[nt][2], Oacc[nt][3]);
    }
}

// ---------------- combine partials, divide (unrolled predicated -> MLP) ----------------
__global__ void final_kernel(float* __restrict__ out)
{
    int idx = blockIdx.x * 256 + threadIdx.x;
    int row = idx >> 4;
    int qt = (row & (TT - 1)) >> 6;
    int kte = qt + 2; if (kte > 32) kte = 32;
    int ns = (kte + 3) >> 2;
    float l = 0.f;
    float4 o = make_float4(0.f, 0.f, 0.f, 0.f);
#pragma unroll
    for (int s = 0; s < 8; s++) {
        if (s < ns) {
            l += g_accL[s][row];
            float4 p = ((const float4*)g_accO[s])[idx];
            o.x += p.x; o.y += p.y; o.z += p.z; o.w += p.w;
        }
    }
    float inv = 1.f / l;
    ((float4*)out)[idx] = make_float4(o.x*inv, o.y*inv, o.z*inv, o.w*inv);
}

extern "C" void kernel_launch(void* const* d_in, const int* in_sizes, int n_in,
                              void* d_out, int out_size)
{
    const float* q  = (const float*)d_in[0];
    const float* k  = (const float*)d_in[1];
    const float* v  = (const float*)d_in[2];
    const float* Wq = (const float*)d_in[3];
    const float* Wk = (const float*)d_in[4];
    const float* Wv = (const float*)d_in[5];
    const int* pad  = (const int*)d_in[6];
    float* out = (float*)d_out;

    const int attn_smem = 36864 + 256;   // double-buffered K/V (fp16) + suffix
    cudaFuncSetAttribute(attn_kernel, cudaFuncAttributeMaxDynamicSharedMemorySize, attn_smem);

    wprep_kernel<<<dim3(3, 128), 256>>>(Wq, Wk, Wv);
    proj_kernel<<<dim3(128, 3), 128>>>(q, k, v);
    attn_kernel<<<604, 128, attn_smem>>>(pad);
    final_kernel<<<BB * TT * HH / 4 / 256, 256>>>(out);
}

// round 15
// speedup vs baseline: 3.3636x; 1.0064x over previous
#include <cuda_runtime.h>
#include <cuda_bf16.h>
#include <cuda_fp16.h>
#include <cstdint>

#define BB 4
#define TT 2048
#define CC 1024
#define HH 64

__device__ uint32_t g_Wp[3][HH][CC/2];             // W packed fp16x2 (single precision)
__device__ uint32_t g_OHi[3][BB*TT*HH/2];          // projected Q/K/V, packed fp16x2 hi
__device__ uint32_t g_OLo[3][BB*TT*HH/2];          // lo (only Q's is consumed)
__device__ float g_Vtile[BB][32][HH];
__device__ float g_accO[8][BB*TT*HH];
__device__ float g_accL[8][BB*TT];

// pack float2 -> fp16x2 hi + fp16x2 lo (split-fp16)
__device__ __forceinline__ void cvt_pairh(float2 f, uint32_t& hi, uint32_t& lo) {
    __half2 h = __float22half2_rn(f);
    hi = *reinterpret_cast<uint32_t*>(&h);
    float2 hf = __half22float2(h);
    __half2 l = __float22half2_rn(make_float2(f.x - hf.x, f.y - hf.y));
    lo = *reinterpret_cast<uint32_t*>(&l);
}

__device__ __forceinline__ void mma_f16(float* c, const uint32_t* a, uint32_t b0, uint32_t b1) {
    asm("mma.sync.aligned.m16n8k16.row.col.f32.f16.f16.f32 "
        "{%0,%1,%2,%3}, {%4,%5,%6,%7}, {%8,%9}, {%0,%1,%2,%3};"
        : "+f"(c[0]), "+f"(c[1]), "+f"(c[2]), "+f"(c[3])
        : "r"(a[0]), "r"(a[1]), "r"(a[2]), "r"(a[3]), "r"(b0), "r"(b1));
}
__device__ __forceinline__ void ldsm4(uint32_t& r0, uint32_t& r1, uint32_t& r2, uint32_t& r3, uint32_t a) {
    asm volatile("ldmatrix.sync.aligned.m8n8.x4.shared.b16 {%0,%1,%2,%3}, [%4];"
                 : "=r"(r0), "=r"(r1), "=r"(r2), "=r"(r3) : "r"(a));
}
__device__ __forceinline__ void ldsm4t(uint32_t& r0, uint32_t& r1, uint32_t& r2, uint32_t& r3, uint32_t a) {
    asm volatile("ldmatrix.sync.aligned.m8n8.x4.trans.shared.b16 {%0,%1,%2,%3}, [%4];"
                 : "=r"(r0), "=r"(r1), "=r"(r2), "=r"(r3) : "r"(a));
}
__device__ __forceinline__ uint32_t smem_u32(const void* p) {
    uint32_t a;
    asm("{ .reg .u64 t; cvta.to.shared.u64 t, %1; cvt.u32.u64 %0, t; }" : "=r"(a) : "l"(p));
    return a;
}
__device__ __forceinline__ void cp16(uint32_t dst, const void* src) {
    asm volatile("cp.async.cg.shared.global [%0], [%1], 16;" :: "r"(dst), "l"(src));
}
#define CP_COMMIT() asm volatile("cp.async.commit_group;" ::: "memory")
#define CP_WAIT1()  asm volatile("cp.async.wait_group 1;" ::: "memory")
#define CP_WAIT0()  asm volatile("cp.async.wait_group 0;" ::: "memory")

// ---------------- W prepack: single fp16 ----------------
__global__ void wprep_kernel(const float* __restrict__ Wq, const float* __restrict__ Wk,
                             const float* __restrict__ Wv)
{
    int z = blockIdx.x;
    const float* W = (z == 0) ? Wq : (z == 1) ? Wk : Wv;
    int idx = blockIdx.y * 256 + threadIdx.x;
    int col = idx & 63, j = idx >> 6;
    __half2 h = __float22half2_rn(make_float2(W[(size_t)(2*j) * HH + col],
                                              W[(size_t)(2*j+1) * HH + col]));
    g_Wp[z][col][j] = *reinterpret_cast<uint32_t*>(&h);
}

// ---------------- Projection: fp16 split-X x single-W (2 MMAs); epilogue fp16 hi/lo + V sums ----
__global__ __launch_bounds__(128) void proj_kernel(
    const float* __restrict__ q, const float* __restrict__ k, const float* __restrict__ v)
{
    int z = blockIdx.y;
    const float* X = (z == 0) ? q : (z == 1) ? k : v;
    const uint32_t* WP = &g_Wp[z][0][0];

    __shared__ uint32_t sB[64][68];
    __shared__ float sVs[4][64];

    int t = threadIdx.x, warp = t >> 5, lane = t & 31;
    int g = lane >> 2, tig = lane & 3;
    int rowC = blockIdx.x * 64;
    int row0 = rowC + warp * 16;

    const float* pA0 = X + (size_t)(row0 + g)     * CC + 2 * tig;
    const float* pA1 = X + (size_t)(row0 + g + 8) * CC + 2 * tig;

    float acc[8][4];
#pragma unroll
    for (int j = 0; j < 8; j++)
#pragma unroll
        for (int e = 0; e < 4; e++) acc[j][e] = 0.f;

    for (int c = 0; c < 8; c++) {
        for (int i = t; i < 1024; i += 128) {
            int col = i >> 4, f4 = (i & 15) << 2;
            *(uint4*)&sB[col][f4] = *(const uint4*)&WP[col * (CC/2) + c * 64 + f4];
        }
        __syncthreads();
#pragma unroll
        for (int s = 0; s < 8; s++) {
            int k0 = c * 128 + s * 16;
            uint32_t ah[4], al[4];
            cvt_pairh(*(const float2*)(pA0 + k0),     ah[0], al[0]);
            cvt_pairh(*(const float2*)(pA1 + k0),     ah[1], al[1]);
            cvt_pairh(*(const float2*)(pA0 + k0 + 8), ah[2], al[2]);
            cvt_pairh(*(const float2*)(pA1 + k0 + 8), ah[3], al[3]);
#pragma unroll
            for (int j = 0; j < 8; j++) {
                int colr = j * 8 + g;
                uint32_t b0 = sB[colr][s*8 + tig], b1 = sB[colr][s*8 + tig + 4];
                mma_f16(acc[j], ah, b0, b1);
                mma_f16(acc[j], al, b0, b1);
            }
        }
        __syncthreads();
    }

    uint32_t* OH = g_OHi[z];
    uint32_t* OL = g_OLo[z];
    int r0 = row0 + g;
#pragma unroll
    for (int j = 0; j < 8; j++) {
        int col = j * 8 + 2 * tig;
        uint32_t hi, lo;
        cvt_pairh(make_float2(acc[j][0], acc[j][1]), hi, lo);
        OH[((size_t)r0 * HH + col) >> 1] = hi;
        if (z == 0) OL[((size_t)r0 * HH + col) >> 1] = lo;
        cvt_pairh(make_float2(acc[j][2], acc[j][3]), hi, lo);
        OH[((size_t)(r0 + 8) * HH + col) >> 1] = hi;
        if (z == 0) OL[((size_t)(r0 + 8) * HH + col) >> 1] = lo;
    }

    // V tile column sums in fp32 (this CTA owns exactly one 64-row tile)
    if (z == 2) {
        float cs0[8], cs1[8];
#pragma unroll
        for (int j = 0; j < 8; j++) {
            cs0[j] = acc[j][0] + acc[j][2];
            cs1[j] = acc[j][1] + acc[j][3];
        }
#pragma unroll
        for (int off = 4; off < 32; off <<= 1)
#pragma unroll
            for (int j = 0; j < 8; j++) {
                cs0[j] += __shfl_xor_sync(0xffffffffu, cs0[j], off);
                cs1[j] += __shfl_xor_sync(0xffffffffu, cs1[j], off);
            }
        if (lane < 4) {
#pragma unroll
            for (int j = 0; j < 8; j++) {
                sVs[warp][j * 8 + 2 * lane] = cs0[j];
                sVs[warp][j * 8 + 2 * lane + 1] = cs1[j];
            }
        }
        __syncthreads();
        if (t < 64) {
            int b2 = rowC >> 11, tb = (rowC & 2047) >> 6;
            g_Vtile[b2][tb][t] = sVs[0][t] + sVs[1][t] + sVs[2][t] + sVs[3][t];
        }
    }
}

// ---------------- Attention: fp16 tensor-core flash; K/V single, Q/P split ---------------
#define SROW 72   // smem tile row stride in fp16 (144 B)
__global__ __launch_bounds__(128, 4) void attn_kernel(const int* __restrict__ pad)
{
    extern __shared__ char dyn[];
    uint32_t base = smem_u32(dyn);
    // double-buffered: buf*18432 + {K:0, V:9216}
    float* sSuf = (float*)(dyn + 36864);

    int u = blockIdx.x;
    int b = u & 3, w = u >> 2;
    int qt = 0, chunk = 0, rem = w;
#pragma unroll 1
    for (int q2 = 31; q2 >= 0; q2--) {
        int kte = q2 + 2; if (kte > 32) kte = 32;
        int s = (kte + 3) >> 2;
        if (rem < s) { qt = q2; chunk = rem; break; }
        rem -= s;
    }
    int kt_end = qt + 2; if (kt_end > 32) kt_end = 32;
    int kt0 = chunk * 4, kt1 = kt0 + 4; if (kt1 > kt_end) kt1 = kt_end;
    bool last = (kt1 == kt_end);
    int qi0 = qt * 64;

    const uint32_t* QH0 = g_OHi[0];
    const uint32_t* QL0 = g_OLo[0];
    const uint4* KH = (const uint4*)g_OHi[1];
    const uint4* VH = (const uint4*)g_OHi[2];

    int t = threadIdx.x, warp = t >> 5, lane = t & 31;
    int g = lane >> 2, tig = lane & 3;
    int r0 = qi0 + warp * 16 + g, r1 = r0 + 8;
    bool pad0 = (pad[b * TT + r0] == 1);
    bool pad1 = (pad[b * TT + r1] == 1);

    int rowA = (lane & 8) + (lane & 7), colA8 = (lane & 16) >> 1;   // V(trans) pattern
    int rowK = ((lane & 16) >> 1) + (lane & 7), colK8 = (lane & 8); // K(B) pattern

    auto stageKV = [&](int kt, int buf) {
        int kj0 = kt * 64;
        uint32_t kb = base + (uint32_t)buf * 18432u;
        for (int i = t; i < 512; i += 128) {
            int rr = i >> 3, c = i & 7;
            size_t src = (size_t)(b * TT + kj0 + rr) * 8 + c;
            uint32_t d = (uint32_t)(rr * 144 + c * 16);
            cp16(kb + d,        KH + src);
            cp16(kb + 9216 + d, VH + src);
        }
    };

    stageKV(kt0, 0);
    CP_COMMIT();

    // Q fragments straight from global (A-frag: a0=(g,2c) a1=(g+8,2c) a2=(g,2c+8) a3=(g+8,2c+8))
    uint32_t qh[4][4], ql[4][4];
    {
        size_t b0 = ((size_t)(b * TT) + r0) * 32 + tig;
        size_t b1 = ((size_t)(b * TT) + r1) * 32 + tig;
#pragma unroll
        for (int j = 0; j < 4; j++) {
            qh[j][0] = QH0[b0 + j*8];     qh[j][1] = QH0[b1 + j*8];
            qh[j][2] = QH0[b0 + j*8 + 4]; qh[j][3] = QH0[b1 + j*8 + 4];
            ql[j][0] = QL0[b0 + j*8];     ql[j][1] = QL0[b1 + j*8];
            ql[j][2] = QL0[b0 + j*8 + 4]; ql[j][3] = QL0[b1 + j*8 + 4];
        }
    }

    float Oacc[8][4];
#pragma unroll
    for (int nt = 0; nt < 8; nt++)
#pragma unroll
        for (int e = 0; e < 4; e++) Oacc[nt][e] = 0.f;
    float lp0 = 0.f, lp1 = 0.f;

#pragma unroll 1
    for (int kt = kt0; kt < kt1; kt++) {
        int buf = (kt - kt0) & 1;
        if (kt + 1 < kt1) { stageKV(kt + 1, buf ^ 1); CP_COMMIT(); CP_WAIT1(); }
        else               CP_WAIT0();
        __syncthreads();

        uint32_t uKh = base + (uint32_t)buf * 18432u;
        uint32_t uVh = uKh + 9216;
        int kj0 = kt * 64;

        // S = Qhi K + Qlo K   (K single-fp16)
        float S[8][4];
#pragma unroll
        for (int nt = 0; nt < 8; nt++)
#pragma unroll
            for (int e = 0; e < 4; e++) S[nt][e] = 0.f;
#pragma unroll
        for (int j = 0; j < 4; j++) {
#pragma unroll
            for (int np = 0; np < 4; np++) {
                uint32_t off = (uint32_t)((np * 16 + rowK) * SROW + j * 16 + colK8) * 2;
                uint32_t kh0, kh1, kh2, kh3;
                ldsm4(kh0, kh1, kh2, kh3, uKh + off);
                mma_f16(S[2*np],   qh[j], kh0, kh1);
                mma_f16(S[2*np],   ql[j], kh0, kh1);
                mma_f16(S[2*np+1], qh[j], kh2, kh3);
                mma_f16(S[2*np+1], ql[j], kh2, kh3);
            }
        }

        // weights: masked -> exactly 1.0; kept -> exp(s/8)
#pragma unroll
        for (int nt = 0; nt < 8; nt++) {
            int col0 = kj0 + nt * 8 + 2 * tig;
            S[nt][0] = (!pad0 && col0     <= r0 + 1) ? __expf(S[nt][0] * 0.125f) : 1.0f;
            S[nt][1] = (!pad0 && col0 + 1 <= r0 + 1) ? __expf(S[nt][1] * 0.125f) : 1.0f;
            S[nt][2] = (!pad1 && col0     <= r1 + 1) ? __expf(S[nt][2] * 0.125f) : 1.0f;
            S[nt][3] = (!pad1 && col0 + 1 <= r1 + 1) ? __expf(S[nt][3] * 0.125f) : 1.0f;
            lp0 += S[nt][0] + S[nt][1];
            lp1 += S[nt][2] + S[nt][3];
        }

        // O += P V (P split fp16 hi/lo; V single-fp16 via ldmatrix.trans)
#pragma unroll
        for (int j = 0; j < 4; j++) {
            uint32_t ah[4], al[4];
            cvt_pairh(make_float2(S[2*j][0],   S[2*j][1]),   ah[0], al[0]);
            cvt_pairh(make_float2(S[2*j][2],   S[2*j][3]),   ah[1], al[1]);
            cvt_pairh(make_float2(S[2*j+1][0], S[2*j+1][1]), ah[2], al[2]);
            cvt_pairh(make_float2(S[2*j+1][2], S[2*j+1][3]), ah[3], al[3]);
#pragma unroll
            for (int np = 0; np < 4; np++) {
                uint32_t off = (uint32_t)((j * 16 + rowA) * SROW + np * 16 + colA8) * 2;
                uint32_t vh0, vh1, vh2, vh3;
                ldsm4t(vh0, vh1, vh2, vh3, uVh + off);
                mma_f16(Oacc[2*np],   ah, vh0, vh1);
                mma_f16(Oacc[2*np],   al, vh0, vh1);
                mma_f16(Oacc[2*np+1], ah, vh2, vh3);
                mma_f16(Oacc[2*np+1], al, vh2, vh3);
            }
        }
        __syncthreads();
    }

    lp0 += __shfl_xor_sync(0xffffffffu, lp0, 1, 4);
    lp0 += __shfl_xor_sync(0xffffffffu, lp0, 2, 4);
    lp1 += __shfl_xor_sync(0xffffffffu, lp1, 1, 4);
    lp1 += __shfl_xor_sync(0xffffffffu, lp1, 2, 4);

    // fully-masked suffix (weight exactly 1.0): fp32 V column sums + count
    if (last && kt_end < 32) {
        if (t < 64) {
            float a = 0.f;
            for (int kt2 = kt_end; kt2 < 32; kt2++) a += g_Vtile[b][kt2][t];
            sSuf[t] = a;
        }
        __syncthreads();
        float cnt = (float)(TT - kt_end * 64);
        lp0 += cnt; lp1 += cnt;
#pragma unroll
        for (int nt = 0; nt < 8; nt++) {
            int col = nt * 8 + 2 * tig;
            float s0 = sSuf[col], s1 = sSuf[col + 1];
            Oacc[nt][0] += s0; Oacc[nt][1] += s1;
            Oacc[nt][2] += s0; Oacc[nt][3] += s1;
        }
    }

    if (tig == 0) {
        g_accL[chunk][(size_t)b * TT + r0] = lp0;
        g_accL[chunk][(size_t)b * TT + r1] = lp1;
    }
#pragma unroll
    for (int nt = 0; nt < 8; nt++) {
        int col = nt * 8 + 2 * tig;
        *(float2*)&g_accO[chunk][((size_t)b * TT + r0) * HH + col] =
            make_float2(Oacc[nt][0], Oacc[nt][1]);
        *(float2*)&g_accO[chunk][((size_t)b * TT + r1) * HH + col] =
            make_float2(Oacc[nt][2], Oacc[nt][3]);
    }
}

// ---------------- combine partials, divide (unrolled predicated -> MLP) ----------------
__global__ void final_kernel(float* __restrict__ out)
{
    int idx = blockIdx.x * 256 + threadIdx.x;
    int row = idx >> 4;
    int qt = (row & (TT - 1)) >> 6;
    int kte = qt + 2; if (kte > 32) kte = 32;
    int ns = (kte + 3) >> 2;
    float l = 0.f;
    float4 o = make_float4(0.f, 0.f, 0.f, 0.f);
#pragma unroll
    for (int s = 0; s < 8; s++) {
        if (s < ns) {
            l += g_accL[s][row];
            float4 p = ((const float4*)g_accO[s])[idx];
            o.x += p.x; o.y += p.y; o.z += p.z; o.w += p.w;
        }
    }
    float inv = 1.f / l;
    ((float4*)out)[idx] = make_float4(o.x*inv, o.y*inv, o.z*inv, o.w*inv);
}

extern "C" void kernel_launch(void* const* d_in, const int* in_sizes, int n_in,
                              void* d_out, int out_size)
{
    const float* q  = (const float*)d_in[0];
    const float* k  = (const float*)d_in[1];
    const float* v  = (const float*)d_in[2];
    const float* Wq = (const float*)d_in[3];
    const float* Wk = (const float*)d_in[4];
    const float* Wv = (const float*)d_in[5];
    const int* pad  = (const int*)d_in[6];
    float* out = (float*)d_out;

    const int attn_smem = 36864 + 256;   // double-buffered K/V (fp16) + suffix
    cudaFuncSetAttribute(attn_kernel, cudaFuncAttributeMaxDynamicSharedMemorySize, attn_smem);

    wprep_kernel<<<dim3(3, 128), 256>>>(Wq, Wk, Wv);
    proj_kernel<<<dim3(128, 3), 128>>>(q, k, v);
    attn_kernel<<<604, 128, attn_smem>>>(pad);
    final_kernel<<<BB * TT * HH / 4 / 256, 256>>>(out);
}

// round 17
// speedup vs baseline: 3.5251x; 1.0480x over previous
#include <cuda_runtime.h>
#include <cuda_bf16.h>
#include <cuda_fp16.h>
#include <cstdint>

#define BB 4
#define TT 2048
#define CC 1024
#define HH 64

__device__ uint32_t g_Wp[3][HH][CC/2];             // W packed fp16x2 (single precision)
__device__ uint32_t g_OHi[3][BB*TT*HH/2];          // projected Q/K/V, packed fp16x2 hi
__device__ uint32_t g_OLo[3][BB*TT*HH/2];          // lo (only Q's is consumed)
__device__ float g_Vtile[BB][32][HH];
__device__ float g_accO[8][BB*TT*HH];
__device__ float g_accL[8][BB*TT];

// pack float2 -> fp16x2 hi + fp16x2 lo (split-fp16)
__device__ __forceinline__ void cvt_pairh(float2 f, uint32_t& hi, uint32_t& lo) {
    __half2 h = __float22half2_rn(f);
    hi = *reinterpret_cast<uint32_t*>(&h);
    float2 hf = __half22float2(h);
    __half2 l = __float22half2_rn(make_float2(f.x - hf.x, f.y - hf.y));
    lo = *reinterpret_cast<uint32_t*>(&l);
}
// pack float2 -> fp16x2 (single)
__device__ __forceinline__ uint32_t packh(float2 f) {
    __half2 h = __float22half2_rn(f);
    return *reinterpret_cast<uint32_t*>(&h);
}

__device__ __forceinline__ void mma_f16(float* c, const uint32_t* a, uint32_t b0, uint32_t b1) {
    asm("mma.sync.aligned.m16n8k16.row.col.f32.f16.f16.f32 "
        "{%0,%1,%2,%3}, {%4,%5,%6,%7}, {%8,%9}, {%0,%1,%2,%3};"
        : "+f"(c[0]), "+f"(c[1]), "+f"(c[2]), "+f"(c[3])
        : "r"(a[0]), "r"(a[1]), "r"(a[2]), "r"(a[3]), "r"(b0), "r"(b1));
}
__device__ __forceinline__ void ldsm4(uint32_t& r0, uint32_t& r1, uint32_t& r2, uint32_t& r3, uint32_t a) {
    asm volatile("ldmatrix.sync.aligned.m8n8.x4.shared.b16 {%0,%1,%2,%3}, [%4];"
                 : "=r"(r0), "=r"(r1), "=r"(r2), "=r"(r3) : "r"(a));
}
__device__ __forceinline__ void ldsm4t(uint32_t& r0, uint32_t& r1, uint32_t& r2, uint32_t& r3, uint32_t a) {
    asm volatile("ldmatrix.sync.aligned.m8n8.x4.trans.shared.b16 {%0,%1,%2,%3}, [%4];"
                 : "=r"(r0), "=r"(r1), "=r"(r2), "=r"(r3) : "r"(a));
}
__device__ __forceinline__ uint32_t smem_u32(const void* p) {
    uint32_t a;
    asm("{ .reg .u64 t; cvta.to.shared.u64 t, %1; cvt.u32.u64 %0, t; }" : "=r"(a) : "l"(p));
    return a;
}
__device__ __forceinline__ void cp16(uint32_t dst, const void* src) {
    asm volatile("cp.async.cg.shared.global [%0], [%1], 16;" :: "r"(dst), "l"(src));
}
#define CP_COMMIT() asm volatile("cp.async.commit_group;" ::: "memory")
#define CP_WAIT1()  asm volatile("cp.async.wait_group 1;" ::: "memory")
#define CP_WAIT0()  asm volatile("cp.async.wait_group 0;" ::: "memory")

// ---------------- W prepack: single fp16 ----------------
__global__ void wprep_kernel(const float* __restrict__ Wq, const float* __restrict__ Wk,
                             const float* __restrict__ Wv)
{
    int z = blockIdx.x;
    const float* W = (z == 0) ? Wq : (z == 1) ? Wk : Wv;
    int idx = blockIdx.y * 256 + threadIdx.x;
    int col = idx & 63, j = idx >> 6;
    g_Wp[z][col][j] = packh(make_float2(W[(size_t)(2*j) * HH + col],
                                        W[(size_t)(2*j+1) * HH + col]));
}

// ---------------- Projection: fp16 split-X x single-W (2 MMAs); epilogue fp16 hi/lo + V sums ----
__global__ __launch_bounds__(128) void proj_kernel(
    const float* __restrict__ q, const float* __restrict__ k, const float* __restrict__ v)
{
    int z = blockIdx.y;
    const float* X = (z == 0) ? q : (z == 1) ? k : v;
    const uint32_t* WP = &g_Wp[z][0][0];

    __shared__ uint32_t sB[64][68];
    __shared__ float sVs[4][64];

    int t = threadIdx.x, warp = t >> 5, lane = t & 31;
    int g = lane >> 2, tig = lane & 3;
    int rowC = blockIdx.x * 64;
    int row0 = rowC + warp * 16;

    const float* pA0 = X + (size_t)(row0 + g)     * CC + 2 * tig;
    const float* pA1 = X + (size_t)(row0 + g + 8) * CC + 2 * tig;

    float acc[8][4];
#pragma unroll
    for (int j = 0; j < 8; j++)
#pragma unroll
        for (int e = 0; e < 4; e++) acc[j][e] = 0.f;

    for (int c = 0; c < 8; c++) {
        for (int i = t; i < 1024; i += 128) {
            int col = i >> 4, f4 = (i & 15) << 2;
            *(uint4*)&sB[col][f4] = *(const uint4*)&WP[col * (CC/2) + c * 64 + f4];
        }
        __syncthreads();
#pragma unroll
        for (int s = 0; s < 8; s++) {
            int k0 = c * 128 + s * 16;
            uint32_t ah[4], al[4];
            cvt_pairh(*(const float2*)(pA0 + k0),     ah[0], al[0]);
            cvt_pairh(*(const float2*)(pA1 + k0),     ah[1], al[1]);
            cvt_pairh(*(const float2*)(pA0 + k0 + 8), ah[2], al[2]);
            cvt_pairh(*(const float2*)(pA1 + k0 + 8), ah[3], al[3]);
#pragma unroll
            for (int j = 0; j < 8; j++) {
                int colr = j * 8 + g;
                uint32_t b0 = sB[colr][s*8 + tig], b1 = sB[colr][s*8 + tig + 4];
                mma_f16(acc[j], ah, b0, b1);
                mma_f16(acc[j], al, b0, b1);
            }
        }
        __syncthreads();
    }

    uint32_t* OH = g_OHi[z];
    uint32_t* OL = g_OLo[z];
    int r0 = row0 + g;
#pragma unroll
    for (int j = 0; j < 8; j++) {
        int col = j * 8 + 2 * tig;
        uint32_t hi, lo;
        cvt_pairh(make_float2(acc[j][0], acc[j][1]), hi, lo);
        OH[((size_t)r0 * HH + col) >> 1] = hi;
        if (z == 0) OL[((size_t)r0 * HH + col) >> 1] = lo;
        cvt_pairh(make_float2(acc[j][2], acc[j][3]), hi, lo);
        OH[((size_t)(r0 + 8) * HH + col) >> 1] = hi;
        if (z == 0) OL[((size_t)(r0 + 8) * HH + col) >> 1] = lo;
    }

    // V tile column sums in fp32 (this CTA owns exactly one 64-row tile)
    if (z == 2) {
        float cs0[8], cs1[8];
#pragma unroll
        for (int j = 0; j < 8; j++) {
            cs0[j] = acc[j][0] + acc[j][2];
            cs1[j] = acc[j][1] + acc[j][3];
        }
#pragma unroll
        for (int off = 4; off < 32; off <<= 1)
#pragma unroll
            for (int j = 0; j < 8; j++) {
                cs0[j] += __shfl_xor_sync(0xffffffffu, cs0[j], off);
                cs1[j] += __shfl_xor_sync(0xffffffffu, cs1[j], off);
            }
        if (lane < 4) {
#pragma unroll
            for (int j = 0; j < 8; j++) {
                sVs[warp][j * 8 + 2 * lane] = cs0[j];
                sVs[warp][j * 8 + 2 * lane + 1] = cs1[j];
            }
        }
        __syncthreads();
        if (t < 64) {
            int b2 = rowC >> 11, tb = (rowC & 2047) >> 6;
            g_Vtile[b2][tb][t] = sVs[0][t] + sVs[1][t] + sVs[2][t] + sVs[3][t];
        }
    }
}

// ---------------- Attention: fp16 flash; K/V/P single, Q split ---------------
#define SROW 72   // smem tile row stride in fp16 (144 B)
__global__ __launch_bounds__(128, 4) void attn_kernel(const int* __restrict__ pad)
{
    extern __shared__ char dyn[];
    uint32_t base = smem_u32(dyn);
    // double-buffered: buf*18432 + {K:0, V:9216}
    float* sSuf = (float*)(dyn + 36864);

    int u = blockIdx.x;
    int b = u & 3, w = u >> 2;
    int qt = 0, chunk = 0, rem = w;
#pragma unroll 1
    for (int q2 = 31; q2 >= 0; q2--) {
        int kte = q2 + 2; if (kte > 32) kte = 32;
        int s = (kte + 3) >> 2;
        if (rem < s) { qt = q2; chunk = rem; break; }
        rem -= s;
    }
    int kt_end = qt + 2; if (kt_end > 32) kt_end = 32;
    int kt0 = chunk * 4, kt1 = kt0 + 4; if (kt1 > kt_end) kt1 = kt_end;
    bool last = (kt1 == kt_end);
    int qi0 = qt * 64;

    const uint32_t* QH0 = g_OHi[0];
    const uint32_t* QL0 = g_OLo[0];
    const uint4* KH = (const uint4*)g_OHi[1];
    const uint4* VH = (const uint4*)g_OHi[2];

    int t = threadIdx.x, warp = t >> 5, lane = t & 31;
    int g = lane >> 2, tig = lane & 3;
    int r0 = qi0 + warp * 16 + g, r1 = r0 + 8;
    bool pad0 = (pad[b * TT + r0] == 1);
    bool pad1 = (pad[b * TT + r1] == 1);

    int rowA = (lane & 8) + (lane & 7), colA8 = (lane & 16) >> 1;   // V(trans) pattern
    int rowK = ((lane & 16) >> 1) + (lane & 7), colK8 = (lane & 8); // K(B) pattern

    auto stageKV = [&](int kt, int buf) {
        int kj0 = kt * 64;
        uint32_t kb = base + (uint32_t)buf * 18432u;
        for (int i = t; i < 512; i += 128) {
            int rr = i >> 3, c = i & 7;
            size_t src = (size_t)(b * TT + kj0 + rr) * 8 + c;
            uint32_t d = (uint32_t)(rr * 144 + c * 16);
            cp16(kb + d,        KH + src);
            cp16(kb + 9216 + d, VH + src);
        }
    };

    stageKV(kt0, 0);
    CP_COMMIT();

    // Q fragments straight from global (A-frag: a0=(g,2c) a1=(g+8,2c) a2=(g,2c+8) a3=(g+8,2c+8))
    uint32_t qh[4][4], ql[4][4];
    {
        size_t b0 = ((size_t)(b * TT) + r0) * 32 + tig;
        size_t b1 = ((size_t)(b * TT) + r1) * 32 + tig;
#pragma unroll
        for (int j = 0; j < 4; j++) {
            qh[j][0] = QH0[b0 + j*8];     qh[j][1] = QH0[b1 + j*8];
            qh[j][2] = QH0[b0 + j*8 + 4]; qh[j][3] = QH0[b1 + j*8 + 4];
            ql[j][0] = QL0[b0 + j*8];     ql[j][1] = QL0[b1 + j*8];
            ql[j][2] = QL0[b0 + j*8 + 4]; ql[j][3] = QL0[b1 + j*8 + 4];
        }
    }

    float Oacc[8][4];
#pragma unroll
    for (int nt = 0; nt < 8; nt++)
#pragma unroll
        for (int e = 0; e < 4; e++) Oacc[nt][e] = 0.f;
    float lp0 = 0.f, lp1 = 0.f;

#pragma unroll 1
    for (int kt = kt0; kt < kt1; kt++) {
        int buf = (kt - kt0) & 1;
        if (kt + 1 < kt1) { stageKV(kt + 1, buf ^ 1); CP_COMMIT(); CP_WAIT1(); }
        else               CP_WAIT0();
        __syncthreads();

        uint32_t uKh = base + (uint32_t)buf * 18432u;
        uint32_t uVh = uKh + 9216;
        int kj0 = kt * 64;

        // S = Qhi K + Qlo K   (K single-fp16)
        float S[8][4];
#pragma unroll
        for (int nt = 0; nt < 8; nt++)
#pragma unroll
            for (int e = 0; e < 4; e++) S[nt][e] = 0.f;
#pragma unroll
        for (int j = 0; j < 4; j++) {
#pragma unroll
            for (int np = 0; np < 4; np++) {
                uint32_t off = (uint32_t)((np * 16 + rowK) * SROW + j * 16 + colK8) * 2;
                uint32_t kh0, kh1, kh2, kh3;
                ldsm4(kh0, kh1, kh2, kh3, uKh + off);
                mma_f16(S[2*np],   qh[j], kh0, kh1);
                mma_f16(S[2*np],   ql[j], kh0, kh1);
                mma_f16(S[2*np+1], qh[j], kh2, kh3);
                mma_f16(S[2*np+1], ql[j], kh2, kh3);
            }
        }

        // weights: masked -> exactly 1.0; kept -> exp(s/8)
#pragma unroll
        for (int nt = 0; nt < 8; nt++) {
            int col0 = kj0 + nt * 8 + 2 * tig;
            S[nt][0] = (!pad0 && col0     <= r0 + 1) ? __expf(S[nt][0] * 0.125f) : 1.0f;
            S[nt][1] = (!pad0 && col0 + 1 <= r0 + 1) ? __expf(S[nt][1] * 0.125f) : 1.0f;
            S[nt][2] = (!pad1 && col0     <= r1 + 1) ? __expf(S[nt][2] * 0.125f) : 1.0f;
            S[nt][3] = (!pad1 && col0 + 1 <= r1 + 1) ? __expf(S[nt][3] * 0.125f) : 1.0f;
            lp0 += S[nt][0] + S[nt][1];
            lp1 += S[nt][2] + S[nt][3];
        }

        // O += P V (P single fp16 -> 8 MMAs; V single-fp16 via ldmatrix.trans)
#pragma unroll
        for (int j = 0; j < 4; j++) {
            uint32_t ah[4];
            ah[0] = packh(make_float2(S[2*j][0],   S[2*j][1]));
            ah[1] = packh(make_float2(S[2*j][2],   S[2*j][3]));
            ah[2] = packh(make_float2(S[2*j+1][0], S[2*j+1][1]));
            ah[3] = packh(make_float2(S[2*j+1][2], S[2*j+1][3]));
#pragma unroll
            for (int np = 0; np < 4; np++) {
                uint32_t off = (uint32_t)((j * 16 + rowA) * SROW + np * 16 + colA8) * 2;
                uint32_t vh0, vh1, vh2, vh3;
                ldsm4t(vh0, vh1, vh2, vh3, uVh + off);
                mma_f16(Oacc[2*np],   ah, vh0, vh1);
                mma_f16(Oacc[2*np+1], ah, vh2, vh3);
            }
        }
        __syncthreads();
    }

    lp0 += __shfl_xor_sync(0xffffffffu, lp0, 1, 4);
    lp0 += __shfl_xor_sync(0xffffffffu, lp0, 2, 4);
    lp1 += __shfl_xor_sync(0xffffffffu, lp1, 1, 4);
    lp1 += __shfl_xor_sync(0xffffffffu, lp1, 2, 4);

    // fully-masked suffix (weight exactly 1.0): fp32 V column sums + count
    if (last && kt_end < 32) {
        if (t < 64) {
            float a = 0.f;
            for (int kt2 = kt_end; kt2 < 32; kt2++) a += g_Vtile[b][kt2][t];
            sSuf[t] = a;
        }
        __syncthreads();
        float cnt = (float)(TT - kt_end * 64);
        lp0 += cnt; lp1 += cnt;
#pragma unroll
        for (int nt = 0; nt < 8; nt++) {
            int col = nt * 8 + 2 * tig;
            float s0 = sSuf[col], s1 = sSuf[col + 1];
            Oacc[nt][0] += s0; Oacc[nt][1] += s1;
            Oacc[nt][2] += s0; Oacc[nt][3] += s1;
        }
    }

    if (tig == 0) {
        g_accL[chunk][(size_t)b * TT + r0] = lp0;
        g_accL[chunk][(size_t)b * TT + r1] = lp1;
    }
#pragma unroll
    for (int nt = 0; nt < 8; nt++) {
        int col = nt * 8 + 2 * tig;
        *(float2*)&g_accO[chunk][((size_t)b * TT + r0) * HH + col] =
            make_float2(Oacc[nt][0], Oacc[nt][1]);
        *(float2*)&g_accO[chunk][((size_t)b * TT + r1) * HH + col] =
            make_float2(Oacc[nt][2], Oacc[nt][3]);
    }
}

// ---------------- combine partials, divide (unrolled predicated -> MLP) ----------------
__global__ void final_kernel(float* __restrict__ out)
{
    int idx = blockIdx.x * 256 + threadIdx.x;
    int row = idx >> 4;
    int qt = (row & (TT - 1)) >> 6;
    int kte = qt + 2; if (kte > 32) kte = 32;
    int ns = (kte + 3) >> 2;
    float l = 0.f;
    float4 o = make_float4(0.f, 0.f, 0.f, 0.f);
#pragma unroll
    for (int s = 0; s < 8; s++) {
        if (s < ns) {
            l += g_accL[s][row];
            float4 p = ((const float4*)g_accO[s])[idx];
            o.x += p.x; o.y += p.y; o.z += p.z; o.w += p.w;
        }
    }
    float inv = 1.f / l;
    ((float4*)out)[idx] = make_float4(o.x*inv, o.y*inv, o.z*inv, o.w*inv);
}

extern "C" void kernel_launch(void* const* d_in, const int* in_sizes, int n_in,
                              void* d_out, int out_size)
{
    const float* q  = (const float*)d_in[0];
    const float* k  = (const float*)d_in[1];
    const float* v  = (const float*)d_in[2];
    const float* Wq = (const float*)d_in[3];
    const float* Wk = (const float*)d_in[4];
    const float* Wv = (const float*)d_in[5];
    const int* pad  = (const int*)d_in[6];
    float* out = (float*)d_out;

    const int attn_smem = 36864 + 256;   // double-buffered K/V (fp16) + suffix
    cudaFuncSetAttribute(attn_kernel, cudaFuncAttributeMaxDynamicSharedMemorySize, attn_smem);

    wprep_kernel<<<dim3(3, 128), 256>>>(Wq, Wk, Wv);
    proj_kernel<<<dim3(128, 3), 128>>>(q, k, v);
    attn_kernel<<<604, 128, attn_smem>>>(pad);
    final_kernel<<<BB * TT * HH / 4 / 256, 256>>>(out);
}